// round 2
// baseline (speedup 1.0000x reference)
#include <cuda_runtime.h>
#include <cuda_bf16.h>

#define D 128
#define TILE 32
#define NTHREADS 128
#define NODES 50000
#define EDGES 500000
#define MAXT 10.0f
#define EIN_STRIDE 260   // 257 padded to multiple of 4 floats

// Scratch (device globals -- no allocation allowed)
__device__ float g_agg[(size_t)NODES * D];   // segment_sum(edge_feat) over row
__device__ float g_ts[(size_t)NODES * 3];    // segment_sum(trans) over row
__device__ float g_cnt[NODES];               // edge counts per row node

__device__ __forceinline__ float silu_f(float x) {
    return x * __fdividef(1.0f, 1.0f + __expf(-x));
}
__device__ __forceinline__ float sigmoid_f(float x) {
    return __fdividef(1.0f, 1.0f + __expf(-x));
}
__device__ __forceinline__ float clampt(float x) {
    return fminf(fmaxf(x, -MAXT), MAXT);
}

__global__ void zero_kernel() {
    int idx = blockIdx.x * blockDim.x + threadIdx.x;
    int stride = gridDim.x * blockDim.x;
    for (int i = idx; i < NODES * D; i += stride) g_agg[i] = 0.0f;
    for (int i = idx; i < NODES * 3; i += stride) g_ts[i] = 0.0f;
    for (int i = idx; i < NODES; i += stride) g_cnt[i] = 0.0f;
}

// ---------------------------------------------------------------------------
// Edge kernel: 32 edges per block, 128 threads (thread j = output feature j).
// ---------------------------------------------------------------------------
__global__ void __launch_bounds__(NTHREADS, 4) edge_kernel(
    const float* __restrict__ h, const int* __restrict__ ei,
    const float* __restrict__ coord,
    const float* __restrict__ We1, const float* __restrict__ be1,
    const float* __restrict__ We2, const float* __restrict__ be2,
    const float* __restrict__ Watt, const float* __restrict__ batt,
    const float* __restrict__ Wc1, const float* __restrict__ bc1,
    const float* __restrict__ Wc2,
    float* __restrict__ edge_out)
{
    extern __shared__ float sm[];
    float* sA   = sm;                         // [32][EIN_STRIDE]  e_in, later edge_feat
    float* sB   = sm + TILE * EIN_STRIDE;     // [32][128]         mid buffer
    float* sCD  = sB + TILE * D;              // [32][4]           coord_diff
    float* sAtt = sCD + TILE * 4;             // [32]
    float* sCw  = sAtt + TILE;                // [32]
    int*   sRow = (int*)(sCw + TILE);         // [32]
    int*   sCol = sRow + TILE;                // [32]

    const int tid  = threadIdx.x;
    const int lane = tid & 31;
    const int warp = tid >> 5;
    const long long e0 = (long long)blockIdx.x * TILE;

    // indices + coord_diff + radial
    if (tid < TILE) {
        long long e = e0 + tid;
        int r = ei[e];
        int c = ei[(long long)EDGES + e];
        sRow[tid] = r;
        sCol[tid] = c;
        float dx = coord[r * 3 + 0] - coord[c * 3 + 0];
        float dy = coord[r * 3 + 1] - coord[c * 3 + 1];
        float dz = coord[r * 3 + 2] - coord[c * 3 + 2];
        sCD[tid * 4 + 0] = dx;
        sCD[tid * 4 + 1] = dy;
        sCD[tid * 4 + 2] = dz;
        sA[tid * EIN_STRIDE + 256] = dx * dx + dy * dy + dz * dz;
    }
    __syncthreads();

    // gather h[row], h[col] (warp w handles edges w*8 .. w*8+7, coalesced)
    for (int i = 0; i < 8; i++) {
        int el = warp * 8 + i;
        const float* hr = h + (long long)sRow[el] * D;
        const float* hc = h + (long long)sCol[el] * D;
        #pragma unroll
        for (int k = 0; k < 4; k++) {
            sA[el * EIN_STRIDE + k * 32 + lane]       = hr[k * 32 + lane];
            sA[el * EIN_STRIDE + 128 + k * 32 + lane] = hc[k * 32 + lane];
        }
    }
    __syncthreads();

    const int j = tid;
    float acc[TILE];

    // ---- Layer 1: e = silu(e_in @ We1 + be1) -> sB
    {
        float b = be1[j];
        #pragma unroll
        for (int e = 0; e < TILE; e++) acc[e] = b;
        for (int k4 = 0; k4 < 64; k4++) {
            int k = k4 * 4;
            float w0 = We1[(k + 0) * D + j];
            float w1 = We1[(k + 1) * D + j];
            float w2 = We1[(k + 2) * D + j];
            float w3 = We1[(k + 3) * D + j];
            #pragma unroll
            for (int e = 0; e < TILE; e++) {
                float4 x = *(const float4*)(sA + e * EIN_STRIDE + k);
                acc[e] = fmaf(x.x, w0, acc[e]);
                acc[e] = fmaf(x.y, w1, acc[e]);
                acc[e] = fmaf(x.z, w2, acc[e]);
                acc[e] = fmaf(x.w, w3, acc[e]);
            }
        }
        float w256 = We1[256 * D + j];
        #pragma unroll
        for (int e = 0; e < TILE; e++) {
            acc[e] = fmaf(sA[e * EIN_STRIDE + 256], w256, acc[e]);
            sB[e * D + j] = silu_f(acc[e]);
        }
    }
    __syncthreads();

    // ---- Layer 2: edge_feat_pre = silu(e @ We2 + be2) -> sA (reuse)
    {
        float b = be2[j];
        #pragma unroll
        for (int e = 0; e < TILE; e++) acc[e] = b;
        for (int k4 = 0; k4 < 32; k4++) {
            int k = k4 * 4;
            float w0 = We2[(k + 0) * D + j];
            float w1 = We2[(k + 1) * D + j];
            float w2 = We2[(k + 2) * D + j];
            float w3 = We2[(k + 3) * D + j];
            #pragma unroll
            for (int e = 0; e < TILE; e++) {
                float4 x = *(const float4*)(sB + e * D + k);
                acc[e] = fmaf(x.x, w0, acc[e]);
                acc[e] = fmaf(x.y, w1, acc[e]);
                acc[e] = fmaf(x.z, w2, acc[e]);
                acc[e] = fmaf(x.w, w3, acc[e]);
            }
        }
        #pragma unroll
        for (int e = 0; e < TILE; e++) sA[e * EIN_STRIDE + j] = silu_f(acc[e]);
    }
    __syncthreads();

    // ---- attention: att[e] = sigmoid(ef_pre[e] . Watt + batt)
    {
        float wa0 = Watt[lane], wa1 = Watt[32 + lane];
        float wa2 = Watt[64 + lane], wa3 = Watt[96 + lane];
        float b0 = batt[0];
        for (int i = 0; i < 8; i++) {
            int el = warp * 8 + i;
            const float* ef = sA + el * EIN_STRIDE;
            float s = ef[lane] * wa0 + ef[32 + lane] * wa1 +
                      ef[64 + lane] * wa2 + ef[96 + lane] * wa3;
            #pragma unroll
            for (int off = 16; off; off >>= 1)
                s += __shfl_xor_sync(0xffffffffu, s, off);
            if (lane == 0) sAtt[el] = sigmoid_f(s + b0);
        }
    }
    __syncthreads();

    // ---- apply attention: write edge_feat + atomic agg
    #pragma unroll
    for (int e = 0; e < TILE; e++) {
        float v = sA[e * EIN_STRIDE + j] * sAtt[e];
        sA[e * EIN_STRIDE + j] = v;
        edge_out[(e0 + e) * D + j] = v;
        atomicAdd(&g_agg[(long long)sRow[e] * D + j], v);
    }
    __syncthreads();

    // ---- coord MLP: cw = silu(ef @ Wc1 + bc1) @ Wc2
    {
        float b = bc1[j];
        float wc2 = Wc2[j];
        #pragma unroll
        for (int e = 0; e < TILE; e++) acc[e] = b;
        for (int k4 = 0; k4 < 32; k4++) {
            int k = k4 * 4;
            float w0 = Wc1[(k + 0) * D + j];
            float w1 = Wc1[(k + 1) * D + j];
            float w2 = Wc1[(k + 2) * D + j];
            float w3 = Wc1[(k + 3) * D + j];
            #pragma unroll
            for (int e = 0; e < TILE; e++) {
                float4 x = *(const float4*)(sA + e * EIN_STRIDE + k);
                acc[e] = fmaf(x.x, w0, acc[e]);
                acc[e] = fmaf(x.y, w1, acc[e]);
                acc[e] = fmaf(x.z, w2, acc[e]);
                acc[e] = fmaf(x.w, w3, acc[e]);
            }
        }
        #pragma unroll
        for (int e = 0; e < TILE; e++) sB[e * D + j] = silu_f(acc[e]) * wc2;
    }
    __syncthreads();

    // reduce rows of sB -> cw[e]
    for (int i = 0; i < 8; i++) {
        int el = warp * 8 + i;
        const float* p = sB + el * D;
        float s = p[lane] + p[32 + lane] + p[64 + lane] + p[96 + lane];
        #pragma unroll
        for (int off = 16; off; off >>= 1)
            s += __shfl_xor_sync(0xffffffffu, s, off);
        if (lane == 0) sCw[el] = s;
    }
    __syncthreads();

    // ---- trans = clip(coord_diff * cw) -> atomic segment sums
    if (tid < TILE) {
        int r = sRow[tid];
        float cw = sCw[tid];
        float tx = clampt(sCD[tid * 4 + 0] * cw);
        float ty = clampt(sCD[tid * 4 + 1] * cw);
        float tz = clampt(sCD[tid * 4 + 2] * cw);
        atomicAdd(&g_ts[r * 3 + 0], tx);
        atomicAdd(&g_ts[r * 3 + 1], ty);
        atomicAdd(&g_ts[r * 3 + 2], tz);
        atomicAdd(&g_cnt[r], 1.0f);
    }
}

// ---------------------------------------------------------------------------
// Node kernel: 32 nodes per block. h_out = h + node_mlp([h, agg]); coord_out.
// ---------------------------------------------------------------------------
__global__ void __launch_bounds__(NTHREADS, 4) node_kernel(
    const float* __restrict__ h, const float* __restrict__ coord,
    const float* __restrict__ Wn1, const float* __restrict__ bn1,
    const float* __restrict__ Wn2, const float* __restrict__ bn2,
    float* __restrict__ h_out, float* __restrict__ coord_out)
{
    extern __shared__ float sm[];
    float* sIn  = sm;             // [32][256]
    float* sMid = sm + 32 * 256;  // [32][128]

    const int tid  = threadIdx.x;
    const int lane = tid & 31;
    const int warp = tid >> 5;
    const int n0 = blockIdx.x * 32;

    for (int i = 0; i < 8; i++) {
        int nl = warp * 8 + i;
        int n = n0 + nl;
        if (n < NODES) {
            #pragma unroll
            for (int k = 0; k < 4; k++) {
                sIn[nl * 256 + k * 32 + lane]       = h[(long long)n * D + k * 32 + lane];
                sIn[nl * 256 + 128 + k * 32 + lane] = g_agg[(long long)n * D + k * 32 + lane];
            }
        } else {
            #pragma unroll
            for (int k = 0; k < 4; k++) {
                sIn[nl * 256 + k * 32 + lane]       = 0.0f;
                sIn[nl * 256 + 128 + k * 32 + lane] = 0.0f;
            }
        }
    }
    __syncthreads();

    const int j = tid;
    float acc[32];
    {
        float b = bn1[j];
        #pragma unroll
        for (int e = 0; e < 32; e++) acc[e] = b;
        for (int k4 = 0; k4 < 64; k4++) {
            int k = k4 * 4;
            float w0 = Wn1[(k + 0) * D + j];
            float w1 = Wn1[(k + 1) * D + j];
            float w2 = Wn1[(k + 2) * D + j];
            float w3 = Wn1[(k + 3) * D + j];
            #pragma unroll
            for (int e = 0; e < 32; e++) {
                float4 x = *(const float4*)(sIn + e * 256 + k);
                acc[e] = fmaf(x.x, w0, acc[e]);
                acc[e] = fmaf(x.y, w1, acc[e]);
                acc[e] = fmaf(x.z, w2, acc[e]);
                acc[e] = fmaf(x.w, w3, acc[e]);
            }
        }
        #pragma unroll
        for (int e = 0; e < 32; e++) sMid[e * D + j] = silu_f(acc[e]);
    }
    __syncthreads();
    {
        float b = bn2[j];
        #pragma unroll
        for (int e = 0; e < 32; e++) acc[e] = b;
        for (int k4 = 0; k4 < 32; k4++) {
            int k = k4 * 4;
            float w0 = Wn2[(k + 0) * D + j];
            float w1 = Wn2[(k + 1) * D + j];
            float w2 = Wn2[(k + 2) * D + j];
            float w3 = Wn2[(k + 3) * D + j];
            #pragma unroll
            for (int e = 0; e < 32; e++) {
                float4 x = *(const float4*)(sMid + e * D + k);
                acc[e] = fmaf(x.x, w0, acc[e]);
                acc[e] = fmaf(x.y, w1, acc[e]);
                acc[e] = fmaf(x.z, w2, acc[e]);
                acc[e] = fmaf(x.w, w3, acc[e]);
            }
        }
        #pragma unroll
        for (int e = 0; e < 32; e++) {
            int n = n0 + e;
            if (n < NODES)
                h_out[(long long)n * D + j] = h[(long long)n * D + j] + acc[e];
        }
    }

    // coord_out = coord + clip(mean(trans), +-10)
    if (tid < 32) {
        int n = n0 + tid;
        if (n < NODES) {
            float c = fmaxf(g_cnt[n], 1.0f);
            #pragma unroll
            for (int d3 = 0; d3 < 3; d3++) {
                float a = g_ts[n * 3 + d3] / c;
                a = fminf(fmaxf(a, -MAXT), MAXT);
                coord_out[n * 3 + d3] = coord[n * 3 + d3] + a;
            }
        }
    }
}

extern "C" void kernel_launch(void* const* d_in, const int* in_sizes, int n_in,
                              void* d_out, int out_size)
{
    const float* h     = (const float*)d_in[0];
    const int*   ei    = (const int*)d_in[1];
    const float* coord = (const float*)d_in[2];
    const float* We1   = (const float*)d_in[3];
    const float* be1   = (const float*)d_in[4];
    const float* We2   = (const float*)d_in[5];
    const float* be2   = (const float*)d_in[6];
    const float* Watt  = (const float*)d_in[7];
    const float* batt  = (const float*)d_in[8];
    const float* Wc1   = (const float*)d_in[9];
    const float* bc1   = (const float*)d_in[10];
    const float* Wc2   = (const float*)d_in[11];
    const float* Wn1   = (const float*)d_in[12];
    const float* bn1   = (const float*)d_in[13];
    const float* Wn2   = (const float*)d_in[14];
    const float* bn2   = (const float*)d_in[15];

    float* out       = (float*)d_out;
    float* h_out     = out;                                // [N, 128]
    float* coord_out = out + (size_t)NODES * D;            // [N, 3]
    float* edge_out  = coord_out + (size_t)NODES * 3;      // [E, 128]

    size_t esm = (size_t)(TILE * EIN_STRIDE + TILE * D + TILE * 4 + TILE + TILE) * sizeof(float)
               + 2 * TILE * sizeof(int);
    size_t nsm = (size_t)(32 * 256 + 32 * 128) * sizeof(float);

    cudaFuncSetAttribute(edge_kernel, cudaFuncAttributeMaxDynamicSharedMemorySize, (int)esm);
    cudaFuncSetAttribute(node_kernel, cudaFuncAttributeMaxDynamicSharedMemorySize, (int)nsm);

    zero_kernel<<<512, 256>>>();
    edge_kernel<<<EDGES / TILE, NTHREADS, esm>>>(h, ei, coord,
        We1, be1, We2, be2, Watt, batt, Wc1, bc1, Wc2, edge_out);
    node_kernel<<<(NODES + 31) / 32, NTHREADS, nsm>>>(h, coord,
        Wn1, bn1, Wn2, bn2, h_out, coord_out);
}

// round 5
// speedup vs baseline: 1.0744x; 1.0744x over previous
#include <cuda_runtime.h>
#include <cuda_bf16.h>

#define D 128
#define TILE 32
#define NTHREADS 128
#define NODES 50000
#define EDGES 500000
#define MAXT 10.0f
#define SROW 36          // transposed-tile row stride in floats (144 B, 16B-aligned)

typedef unsigned long long ull;

// Scratch (device globals -- no allocation allowed)
__device__ float g_agg[(size_t)NODES * D];   // segment_sum(edge_feat) over row
__device__ float g_ts[(size_t)NODES * 3];    // segment_sum(trans) over row
__device__ float g_cnt[NODES];               // edge counts per row node

__device__ __forceinline__ float silu_f(float x) {
    return x * __fdividef(1.0f, 1.0f + __expf(-x));
}
__device__ __forceinline__ float sigmoid_f(float x) {
    return __fdividef(1.0f, 1.0f + __expf(-x));
}
__device__ __forceinline__ float clampt(float x) {
    return fminf(fmaxf(x, -MAXT), MAXT);
}

__device__ __forceinline__ ull pk2(float lo, float hi) {
    ull r; asm("mov.b64 %0, {%1, %2};" : "=l"(r) : "f"(lo), "f"(hi)); return r;
}
__device__ __forceinline__ void upk2(ull v, float& lo, float& hi) {
    asm("mov.b64 {%0, %1}, %2;" : "=f"(lo), "=f"(hi) : "l"(v));
}
__device__ __forceinline__ void fma2(ull& d, ull a, ull b) {
    asm("fma.rn.f32x2 %0, %1, %2, %0;" : "+l"(d) : "l"(a), "l"(b));
}

// One GEMM step: acc[i] covers edges (2i, 2i+1); xrow = transposed activation row k
__device__ __forceinline__ void gemm_step(ull acc[16], const float* xrow, ull ww) {
    const ulonglong2* p = (const ulonglong2*)xrow;
    #pragma unroll
    for (int ep = 0; ep < 8; ep++) {
        ulonglong2 v = p[ep];
        fma2(acc[2 * ep + 0], v.x, ww);
        fma2(acc[2 * ep + 1], v.y, ww);
    }
}

__global__ void zero_kernel() {
    int idx = blockIdx.x * blockDim.x + threadIdx.x;
    int stride = gridDim.x * blockDim.x;
    for (int i = idx; i < NODES * D; i += stride) g_agg[i] = 0.0f;
    for (int i = idx; i < NODES * 3; i += stride) g_ts[i] = 0.0f;
    for (int i = idx; i < NODES; i += stride) g_cnt[i] = 0.0f;
}

// SMEM float offsets (edge kernel)
#define SX    0                      // [257][SROW] e_in transposed; rows 0..127 reused for ef
#define SMID  (257 * SROW)           // [128][SROW]
#define SCD   (SMID + 128 * SROW)    // [32][4]
#define SATT  (SCD + 128)            // [32]
#define SCW   (SATT + 32)            // [32]
#define SIDX  (SCW + 32)             // 64 ints
#define ESM_FLOATS (SIDX + 64)
#define SCM   (SX + 128 * SROW)      // overlay [32][132] inside sX rows >= 128

// ---------------------------------------------------------------------------
// Edge kernel: 32 edges/block, 128 threads (thread j = output feature j).
// ---------------------------------------------------------------------------
__global__ void __launch_bounds__(NTHREADS, 4) edge_kernel(
    const float* __restrict__ h, const int* __restrict__ ei,
    const float* __restrict__ coord,
    const float* __restrict__ We1, const float* __restrict__ be1,
    const float* __restrict__ We2, const float* __restrict__ be2,
    const float* __restrict__ Watt, const float* __restrict__ batt,
    const float* __restrict__ Wc1, const float* __restrict__ bc1,
    const float* __restrict__ Wc2,
    float* __restrict__ edge_out)
{
    extern __shared__ float sm[];
    int* sRow = (int*)(sm + SIDX);
    int* sCol = sRow + 32;

    const int tid  = threadIdx.x;
    const int lane = tid & 31;
    const int warp = tid >> 5;
    const long long e0 = (long long)blockIdx.x * TILE;

    // indices + coord_diff + radial (radial -> transposed row 256)
    if (tid < TILE) {
        long long e = e0 + tid;
        int r = ei[e];
        int c = ei[(long long)EDGES + e];
        sRow[tid] = r;
        sCol[tid] = c;
        float dx = coord[r * 3 + 0] - coord[c * 3 + 0];
        float dy = coord[r * 3 + 1] - coord[c * 3 + 1];
        float dz = coord[r * 3 + 2] - coord[c * 3 + 2];
        sm[SCD + tid * 4 + 0] = dx;
        sm[SCD + tid * 4 + 1] = dy;
        sm[SCD + tid * 4 + 2] = dz;
        sm[SX + 256 * SROW + tid] = dx * dx + dy * dy + dz * dz;
    }
    __syncthreads();

    // gather h[row] -> rows 0..127, h[col] -> rows 128..255 (transposed [k][e])
    for (int i = 0; i < 8; i++) {
        int el = warp * 8 + i;
        const float* hr = h + (long long)sRow[el] * D;
        const float* hc = h + (long long)sCol[el] * D;
        #pragma unroll
        for (int k0 = 0; k0 < 4; k0++) {
            int k = k0 * 32 + lane;
            sm[SX + k * SROW + el]         = hr[k];
            sm[SX + (128 + k) * SROW + el] = hc[k];
        }
    }
    __syncthreads();

    const int j = tid;
    ull acc[16];

    // ---- Layer 1: silu(e_in @ We1 + be1) -> sMid (transposed)
    {
        float b = be1[j];
        ull bb = pk2(b, b);
        #pragma unroll
        for (int i = 0; i < 16; i++) acc[i] = bb;
        #pragma unroll 4
        for (int k = 0; k < 257; k++) {
            float w = We1[k * D + j];
            ull ww = pk2(w, w);
            gemm_step(acc, sm + SX + k * SROW, ww);
        }
        #pragma unroll
        for (int i = 0; i < 16; i++) {
            float f0, f1; upk2(acc[i], f0, f1);
            *(ull*)(sm + SMID + j * SROW + 2 * i) = pk2(silu_f(f0), silu_f(f1));
        }
    }
    __syncthreads();

    // ---- Layer 2: ef_pre = silu(mid @ We2 + be2) -> sX rows 0..127
    {
        float b = be2[j];
        ull bb = pk2(b, b);
        #pragma unroll
        for (int i = 0; i < 16; i++) acc[i] = bb;
        #pragma unroll 4
        for (int k = 0; k < 128; k++) {
            float w = We2[k * D + j];
            ull ww = pk2(w, w);
            gemm_step(acc, sm + SMID + k * SROW, ww);
        }
        #pragma unroll
        for (int i = 0; i < 16; i++) {
            float f0, f1; upk2(acc[i], f0, f1);
            *(ull*)(sm + SX + j * SROW + 2 * i) = pk2(silu_f(f0), silu_f(f1));
        }
    }
    __syncthreads();

    // ---- attention: att[e] = sigmoid(ef_pre[e] . Watt + batt)
    {
        float b0 = batt[0];
        for (int i = 0; i < 8; i++) {
            int el = warp * 8 + i;
            float s = 0.0f;
            #pragma unroll
            for (int k0 = 0; k0 < 4; k0++) {
                int k = k0 * 32 + lane;
                s = fmaf(sm[SX + k * SROW + el], Watt[k], s);
            }
            #pragma unroll
            for (int off = 16; off; off >>= 1)
                s += __shfl_xor_sync(0xffffffffu, s, off);
            if (lane == 0) sm[SATT + el] = sigmoid_f(s + b0);
        }
    }
    __syncthreads();

    // ---- apply attention: in-place scale + write edge_feat + atomic agg
    for (int i = 0; i < 8; i++) {
        int el = warp * 8 + i;
        float ae = sm[SATT + el];
        int r = sRow[el];
        #pragma unroll
        for (int k0 = 0; k0 < 4; k0++) {
            int k = k0 * 32 + lane;
            float v = sm[SX + k * SROW + el] * ae;
            sm[SX + k * SROW + el] = v;
            edge_out[(e0 + el) * D + k] = v;
            atomicAdd(&g_agg[(long long)r * D + k], v);
        }
    }
    __syncthreads();

    // ---- coord MLP: silu(ef @ Wc1 + bc1) * Wc2[j] -> sCM[e][j]
    {
        float b = bc1[j];
        float wc2 = Wc2[j];
        ull bb = pk2(b, b);
        #pragma unroll
        for (int i = 0; i < 16; i++) acc[i] = bb;
        #pragma unroll 4
        for (int k = 0; k < 128; k++) {
            float w = Wc1[k * D + j];
            ull ww = pk2(w, w);
            gemm_step(acc, sm + SX + k * SROW, ww);
        }
        #pragma unroll
        for (int i = 0; i < 16; i++) {
            float f0, f1; upk2(acc[i], f0, f1);
            sm[SCM + (2 * i + 0) * 132 + j] = silu_f(f0) * wc2;
            sm[SCM + (2 * i + 1) * 132 + j] = silu_f(f1) * wc2;
        }
    }
    __syncthreads();

    // reduce over j -> cw[e]
    for (int i = 0; i < 8; i++) {
        int el = warp * 8 + i;
        const float* p = sm + SCM + el * 132;
        float s = p[lane] + p[32 + lane] + p[64 + lane] + p[96 + lane];
        #pragma unroll
        for (int off = 16; off; off >>= 1)
            s += __shfl_xor_sync(0xffffffffu, s, off);
        if (lane == 0) sm[SCW + el] = s;
    }
    __syncthreads();

    // ---- trans = clip(coord_diff * cw) -> atomic segment sums
    if (tid < TILE) {
        int r = sRow[tid];
        float cw = sm[SCW + tid];
        float tx = clampt(sm[SCD + tid * 4 + 0] * cw);
        float ty = clampt(sm[SCD + tid * 4 + 1] * cw);
        float tz = clampt(sm[SCD + tid * 4 + 2] * cw);
        atomicAdd(&g_ts[r * 3 + 0], tx);
        atomicAdd(&g_ts[r * 3 + 1], ty);
        atomicAdd(&g_ts[r * 3 + 2], tz);
        atomicAdd(&g_cnt[r], 1.0f);
    }
}

// SMEM float offsets (node kernel)
#define SXN   0                     // [256][SROW]
#define SMIDN (256 * SROW)          // [128][SROW]
#define NSM_FLOATS (SMIDN + 128 * SROW)

// ---------------------------------------------------------------------------
// Node kernel: 32 nodes/block. h_out = h + node_mlp([h, agg]); coord_out.
// ---------------------------------------------------------------------------
__global__ void __launch_bounds__(NTHREADS, 4) node_kernel(
    const float* __restrict__ h, const float* __restrict__ coord,
    const float* __restrict__ Wn1, const float* __restrict__ bn1,
    const float* __restrict__ Wn2, const float* __restrict__ bn2,
    float* __restrict__ h_out, float* __restrict__ coord_out)
{
    extern __shared__ float sm[];
    const int tid  = threadIdx.x;
    const int lane = tid & 31;
    const int warp = tid >> 5;
    const int n0 = blockIdx.x * 32;

    // gather [h | agg] transposed
    for (int i = 0; i < 8; i++) {
        int nl = warp * 8 + i;
        int n = n0 + nl;
        if (n < NODES) {
            #pragma unroll
            for (int k0 = 0; k0 < 4; k0++) {
                int k = k0 * 32 + lane;
                sm[SXN + k * SROW + nl]         = h[(long long)n * D + k];
                sm[SXN + (128 + k) * SROW + nl] = g_agg[(long long)n * D + k];
            }
        } else {
            #pragma unroll
            for (int k0 = 0; k0 < 4; k0++) {
                int k = k0 * 32 + lane;
                sm[SXN + k * SROW + nl]         = 0.0f;
                sm[SXN + (128 + k) * SROW + nl] = 0.0f;
            }
        }
    }
    __syncthreads();

    const int j = tid;
    ull acc[16];
    {
        float b = bn1[j];
        ull bb = pk2(b, b);
        #pragma unroll
        for (int i = 0; i < 16; i++) acc[i] = bb;
        #pragma unroll 4
        for (int k = 0; k < 256; k++) {
            float w = Wn1[k * D + j];
            ull ww = pk2(w, w);
            gemm_step(acc, sm + SXN + k * SROW, ww);
        }
        #pragma unroll
        for (int i = 0; i < 16; i++) {
            float f0, f1; upk2(acc[i], f0, f1);
            *(ull*)(sm + SMIDN + j * SROW + 2 * i) = pk2(silu_f(f0), silu_f(f1));
        }
    }
    __syncthreads();
    {
        float b = bn2[j];
        ull bb = pk2(b, b);
        #pragma unroll
        for (int i = 0; i < 16; i++) acc[i] = bb;
        #pragma unroll 4
        for (int k = 0; k < 128; k++) {
            float w = Wn2[k * D + j];
            ull ww = pk2(w, w);
            gemm_step(acc, sm + SMIDN + k * SROW, ww);
        }
        #pragma unroll
        for (int i = 0; i < 16; i++) {
            float f0, f1; upk2(acc[i], f0, f1);
            int na = n0 + 2 * i, nb = na + 1;
            if (na < NODES) h_out[(long long)na * D + j] = h[(long long)na * D + j] + f0;
            if (nb < NODES) h_out[(long long)nb * D + j] = h[(long long)nb * D + j] + f1;
        }
    }

    // coord_out = coord + clip(mean(trans), +-10)
    if (tid < 32) {
        int n = n0 + tid;
        if (n < NODES) {
            float c = fmaxf(g_cnt[n], 1.0f);
            #pragma unroll
            for (int d3 = 0; d3 < 3; d3++) {
                float a = g_ts[n * 3 + d3] / c;
                a = fminf(fmaxf(a, -MAXT), MAXT);
                coord_out[n * 3 + d3] = coord[n * 3 + d3] + a;
            }
        }
    }
}

extern "C" void kernel_launch(void* const* d_in, const int* in_sizes, int n_in,
                              void* d_out, int out_size)
{
    const float* h     = (const float*)d_in[0];
    const int*   ei    = (const int*)d_in[1];
    const float* coord = (const float*)d_in[2];
    const float* We1   = (const float*)d_in[3];
    const float* be1   = (const float*)d_in[4];
    const float* We2   = (const float*)d_in[5];
    const float* be2   = (const float*)d_in[6];
    const float* Watt  = (const float*)d_in[7];
    const float* batt  = (const float*)d_in[8];
    const float* Wc1   = (const float*)d_in[9];
    const float* bc1   = (const float*)d_in[10];
    const float* Wc2   = (const float*)d_in[11];
    const float* Wn1   = (const float*)d_in[12];
    const float* bn1   = (const float*)d_in[13];
    const float* Wn2   = (const float*)d_in[14];
    const float* bn2   = (const float*)d_in[15];

    float* out       = (float*)d_out;
    float* h_out     = out;                                // [N, 128]
    float* coord_out = out + (size_t)NODES * D;            // [N, 3]
    float* edge_out  = coord_out + (size_t)NODES * 3;      // [E, 128]

    size_t esm = (size_t)ESM_FLOATS * sizeof(float);
    size_t nsm = (size_t)NSM_FLOATS * sizeof(float);

    cudaFuncSetAttribute(edge_kernel, cudaFuncAttributeMaxDynamicSharedMemorySize, (int)esm);
    cudaFuncSetAttribute(node_kernel, cudaFuncAttributeMaxDynamicSharedMemorySize, (int)nsm);

    zero_kernel<<<512, 256>>>();
    edge_kernel<<<EDGES / TILE, NTHREADS, esm>>>(h, ei, coord,
        We1, be1, We2, be2, Watt, batt, Wc1, bc1, Wc2, edge_out);
    node_kernel<<<(NODES + 31) / 32, NTHREADS, nsm>>>(h, coord,
        Wn1, bn1, Wn2, bn2, h_out, coord_out);
}

// round 6
// speedup vs baseline: 1.9835x; 1.8462x over previous
#include <cuda_runtime.h>
#include <cuda_bf16.h>
#include <stdint.h>

#define D 128
#define NODES 50000
#define EDGES 500000
#define MAXT 10.0f

#define TE 64            // edges per CTA (edge kernel)
#define RS1 268          // sA row stride (264 used cols, mod32=12 -> conflict-free)
#define RS2 140          // sMid/sEf row stride (136 used cols, mod32=12)
#define NKS1 33          // K=264/8  (256 feats + radial + bias + pad)
#define NKS2 17          // K=136/8  (128 feats + bias + pad)

typedef unsigned long long ull;

// ---------------- device scratch ----------------
__device__ float g_agg[(size_t)NODES * D];
__device__ float g_ts[(size_t)NODES * 3];
__device__ float g_cnt[NODES];
__device__ float4 g_wf1[NKS1 * 8 * 32];   // We1 (+be1) fragment-ordered
__device__ float4 g_wf2[NKS2 * 8 * 32];   // We2 (+be2)
__device__ float4 g_wf3[NKS2 * 8 * 32];   // Wc1 (+bc1)

// ---------------- helpers ----------------
__device__ __forceinline__ float silu_f(float x) {
    return x * __fdividef(1.0f, 1.0f + __expf(-x));
}
__device__ __forceinline__ float sigmoid_f(float x) {
    return __fdividef(1.0f, 1.0f + __expf(-x));
}
__device__ __forceinline__ float clampt(float x) {
    return fminf(fmaxf(x, -MAXT), MAXT);
}
__device__ __forceinline__ uint32_t tfbits(float x) {
    uint32_t u; asm("cvt.rna.tf32.f32 %0, %1;" : "=r"(u) : "f"(x)); return u;
}
__device__ __forceinline__ float tf32r(float x) { return __uint_as_float(tfbits(x)); }

__device__ __forceinline__ void mma8(float acc[4],
    uint32_t a0, uint32_t a1, uint32_t a2, uint32_t a3, uint32_t b0, uint32_t b1)
{
    asm volatile(
        "mma.sync.aligned.m16n8k8.row.col.f32.tf32.tf32.f32 "
        "{%0,%1,%2,%3}, {%4,%5,%6,%7}, {%8,%9}, {%0,%1,%2,%3};"
        : "+f"(acc[0]), "+f"(acc[1]), "+f"(acc[2]), "+f"(acc[3])
        : "r"(a0), "r"(a1), "r"(a2), "r"(a3), "r"(b0), "r"(b1));
}

// one dense layer: acc[16][4] += A(16 rows of this warp) @ B(128 out)
template<int NKS>
__device__ __forceinline__ void run_layer(
    const uint32_t* __restrict__ sact, int rs,
    const float4* __restrict__ wfl,   // already + lane
    float acc[16][4], int rloc, int c)
{
    const uint32_t* alo = sact + rloc * rs + c;
    const uint32_t* ahi = alo + 8 * rs;
    #pragma unroll 4
    for (int ks = 0; ks < NKS; ks++) {
        uint32_t a0 = alo[ks * 8],     a2 = alo[ks * 8 + 4];
        uint32_t a1 = ahi[ks * 8],     a3 = ahi[ks * 8 + 4];
        const float4* wk = wfl + ks * 256;
        #pragma unroll
        for (int p = 0; p < 8; p++) {
            float4 b = wk[p * 32];
            mma8(acc[2 * p],     a0, a1, a2, a3, __float_as_uint(b.x), __float_as_uint(b.y));
            mma8(acc[2 * p + 1], a0, a1, a2, a3, __float_as_uint(b.z), __float_as_uint(b.w));
        }
    }
}

// ---------------- zero + weight prep ----------------
__global__ void zero_kernel() {
    int idx = blockIdx.x * blockDim.x + threadIdx.x;
    int stride = gridDim.x * blockDim.x;
    for (int i = idx; i < NODES * D; i += stride) g_agg[i] = 0.0f;
    for (int i = idx; i < NODES * 3; i += stride) g_ts[i] = 0.0f;
    for (int i = idx; i < NODES; i += stride) g_cnt[i] = 0.0f;
}

__device__ __forceinline__ float wb(const float* W, const float* b, int K, int k, int n) {
    if (k < K) return W[k * D + n];
    if (k == K) return b[n];
    return 0.0f;
}

__global__ void prep_kernel(
    const float* __restrict__ We1, const float* __restrict__ be1,
    const float* __restrict__ We2, const float* __restrict__ be2,
    const float* __restrict__ Wc1, const float* __restrict__ bc1)
{
    int t = blockIdx.x * blockDim.x + threadIdx.x;
    const int n1 = NKS1 * 8 * 32, n2 = NKS2 * 8 * 32;
    const float *W, *bi; int K; float4* dst; int idx;
    if (t < n1)                { W = We1; bi = be1; K = 257; dst = g_wf1; idx = t; }
    else if (t < n1 + n2)      { W = We2; bi = be2; K = 128; dst = g_wf2; idx = t - n1; }
    else if (t < n1 + 2 * n2)  { W = Wc1; bi = bc1; K = 128; dst = g_wf3; idx = t - n1 - n2; }
    else return;
    int lane = idx & 31, p = (idx >> 5) & 7, ks = idx >> 8;
    int c = lane & 3, r = lane >> 2, k0 = ks * 8;
    float4 v;
    v.x = tf32r(wb(W, bi, K, k0 + c,     p * 16 + r));
    v.y = tf32r(wb(W, bi, K, k0 + 4 + c, p * 16 + r));
    v.z = tf32r(wb(W, bi, K, k0 + c,     p * 16 + 8 + r));
    v.w = tf32r(wb(W, bi, K, k0 + 4 + c, p * 16 + 8 + r));
    dst[idx] = v;
}

// ---------------- edge kernel ----------------
// SMEM word offsets
#define O_SA    0
#define O_SMID  (TE * RS1)                  // 17152
#define O_SCD   (O_SMID + TE * RS2)         // 26112
#define O_SROW  (O_SCD + TE * 4)            // 26368
#define O_SCOL  (O_SROW + TE)               // 26432
#define ESM_WORDS (O_SCOL + TE)             // 26496 words = 105984 B
#define O_SEF   O_SA                        // sEf reuses sA region, stride RS2

__global__ void __launch_bounds__(128) edge_kernel(
    const float* __restrict__ h, const int* __restrict__ ei,
    const float* __restrict__ coord,
    const float* __restrict__ Watt, const float* __restrict__ batt,
    const float* __restrict__ Wc2,
    float* __restrict__ edge_out)
{
    extern __shared__ uint32_t smu[];
    float* smf = (float*)smu;
    int*   sRow = (int*)(smu + O_SROW);
    int*   sCol = (int*)(smu + O_SCOL);

    const int tid  = threadIdx.x;
    const int lane = tid & 31;
    const int warp = tid >> 5;
    const int c    = lane & 3;
    const int r4   = lane >> 2;
    const int rloc = warp * 16 + r4;          // this thread's low row in tile
    const long long e0 = (long long)blockIdx.x * TE;

    // ---- gather: indices, coord_diff, radial+bias cols ----
    if (lane < 16) {
        int el = warp * 16 + lane;
        long long e = e0 + el;
        int rr = 0, cc = 0; float dx = 0, dy = 0, dz = 0, rad = 0;
        if (e < EDGES) {
            rr = ei[e]; cc = ei[(long long)EDGES + e];
            dx = coord[rr * 3 + 0] - coord[cc * 3 + 0];
            dy = coord[rr * 3 + 1] - coord[cc * 3 + 1];
            dz = coord[rr * 3 + 2] - coord[cc * 3 + 2];
            rad = dx * dx + dy * dy + dz * dz;
        }
        sRow[el] = rr; sCol[el] = cc;
        smf[O_SCD + el * 4 + 0] = dx;
        smf[O_SCD + el * 4 + 1] = dy;
        smf[O_SCD + el * 4 + 2] = dz;
        float4 z1 = make_float4(tf32r(rad), 1.0f, 0.0f, 0.0f);
        float4 z0 = make_float4(0.0f, 0.0f, 0.0f, 0.0f);
        *(float4*)(smf + O_SA + el * RS1 + 256) = z1;
        *(float4*)(smf + O_SA + el * RS1 + 260) = z0;
    }
    __syncwarp();

    // ---- gather h[row], h[col] -> sA (tf32) ----
    for (int i = 0; i < 16; i++) {
        int el = warp * 16 + i;
        int rr = sRow[el], cc = sCol[el];
        float4 v = *(const float4*)(h + (long long)rr * D + lane * 4);
        float4 w = *(const float4*)(h + (long long)cc * D + lane * 4);
        float4 tv = make_float4(tf32r(v.x), tf32r(v.y), tf32r(v.z), tf32r(v.w));
        float4 tw = make_float4(tf32r(w.x), tf32r(w.y), tf32r(w.z), tf32r(w.w));
        *(float4*)(smf + O_SA + el * RS1 + lane * 4) = tv;
        *(float4*)(smf + O_SA + el * RS1 + 128 + lane * 4) = tw;
    }
    __syncwarp();

    float acc[16][4];
    #pragma unroll
    for (int i = 0; i < 16; i++) { acc[i][0]=0; acc[i][1]=0; acc[i][2]=0; acc[i][3]=0; }

    // ================= Layer 1 =================
    run_layer<NKS1>(smu + O_SA, RS1, g_wf1 + lane, acc, rloc, c);

    // epilogue: silu -> tf32 -> sMid; reset acc
    #pragma unroll
    for (int nt = 0; nt < 16; nt++) {
        int n0 = nt * 8 + 2 * c;
        uint2 lo = make_uint2(tfbits(silu_f(acc[nt][0])), tfbits(silu_f(acc[nt][1])));
        uint2 hi = make_uint2(tfbits(silu_f(acc[nt][2])), tfbits(silu_f(acc[nt][3])));
        *(uint2*)(smu + O_SMID + rloc * RS2 + n0) = lo;
        *(uint2*)(smu + O_SMID + (rloc + 8) * RS2 + n0) = hi;
        acc[nt][0]=0; acc[nt][1]=0; acc[nt][2]=0; acc[nt][3]=0;
    }
    if (lane < 16) {
        int row = warp * 16 + lane;
        *(float4*)(smf + O_SMID + row * RS2 + 128) = make_float4(1.0f, 0, 0, 0);
        *(float4*)(smf + O_SMID + row * RS2 + 132) = make_float4(0, 0, 0, 0);
    }
    __syncwarp();

    // ================= Layer 2 =================
    run_layer<NKS2>(smu + O_SMID, RS2, g_wf2 + lane, acc, rloc, c);

    // attention + apply + stores + agg atomics + sEf
    {
        float batt0 = batt[0];
        float plo = 0.0f, phi = 0.0f;
        #pragma unroll
        for (int nt = 0; nt < 16; nt++) {
            int n0 = nt * 8 + 2 * c;
            float2 wa = *(const float2*)(Watt + n0);
            acc[nt][0] = silu_f(acc[nt][0]); acc[nt][1] = silu_f(acc[nt][1]);
            acc[nt][2] = silu_f(acc[nt][2]); acc[nt][3] = silu_f(acc[nt][3]);
            plo += acc[nt][0] * wa.x + acc[nt][1] * wa.y;
            phi += acc[nt][2] * wa.x + acc[nt][3] * wa.y;
        }
        plo += __shfl_xor_sync(0xffffffffu, plo, 1);
        plo += __shfl_xor_sync(0xffffffffu, plo, 2);
        phi += __shfl_xor_sync(0xffffffffu, phi, 1);
        phi += __shfl_xor_sync(0xffffffffu, phi, 2);
        float attlo = sigmoid_f(plo + batt0);
        float atthi = sigmoid_f(phi + batt0);

        int  elo = rloc, ehi = rloc + 8;
        bool vlo = (e0 + elo) < EDGES, vhi = (e0 + ehi) < EDGES;
        long long glo = (long long)sRow[elo] * D;
        long long ghi = (long long)sRow[ehi] * D;
        float* out_lo = edge_out + (e0 + elo) * D;
        float* out_hi = edge_out + (e0 + ehi) * D;

        #pragma unroll
        for (int nt = 0; nt < 16; nt++) {
            int n0 = nt * 8 + 2 * c;
            float f0 = acc[nt][0] * attlo, f1 = acc[nt][1] * attlo;
            float f2 = acc[nt][2] * atthi, f3 = acc[nt][3] * atthi;
            if (vlo) {
                *(float2*)(out_lo + n0) = make_float2(f0, f1);
                atomicAdd(g_agg + glo + n0,     f0);
                atomicAdd(g_agg + glo + n0 + 1, f1);
            }
            if (vhi) {
                *(float2*)(out_hi + n0) = make_float2(f2, f3);
                atomicAdd(g_agg + ghi + n0,     f2);
                atomicAdd(g_agg + ghi + n0 + 1, f3);
            }
            *(uint2*)(smu + O_SEF + elo * RS2 + n0) = make_uint2(tfbits(f0), tfbits(f1));
            *(uint2*)(smu + O_SEF + ehi * RS2 + n0) = make_uint2(tfbits(f2), tfbits(f3));
            acc[nt][0]=0; acc[nt][1]=0; acc[nt][2]=0; acc[nt][3]=0;
        }
        if (lane < 16) {
            int row = warp * 16 + lane;
            *(float4*)(smf + O_SEF + row * RS2 + 128) = make_float4(1.0f, 0, 0, 0);
            *(float4*)(smf + O_SEF + row * RS2 + 132) = make_float4(0, 0, 0, 0);
        }
        __syncwarp();
    }

    // ================= Layer 3 (coord MLP) =================
    run_layer<NKS2>(smu + O_SEF, RS2, g_wf3 + lane, acc, rloc, c);
    {
        float qlo = 0.0f, qhi = 0.0f;
        #pragma unroll
        for (int nt = 0; nt < 16; nt++) {
            int n0 = nt * 8 + 2 * c;
            float2 w2 = *(const float2*)(Wc2 + n0);
            qlo += silu_f(acc[nt][0]) * w2.x + silu_f(acc[nt][1]) * w2.y;
            qhi += silu_f(acc[nt][2]) * w2.x + silu_f(acc[nt][3]) * w2.y;
        }
        qlo += __shfl_xor_sync(0xffffffffu, qlo, 1);
        qlo += __shfl_xor_sync(0xffffffffu, qlo, 2);
        qhi += __shfl_xor_sync(0xffffffffu, qhi, 1);
        qhi += __shfl_xor_sync(0xffffffffu, qhi, 2);

        if (c == 0) {
            int elo = rloc, ehi = rloc + 8;
            if (e0 + elo < EDGES) {
                int n = sRow[elo];
                atomicAdd(g_ts + n * 3 + 0, clampt(smf[O_SCD + elo * 4 + 0] * qlo));
                atomicAdd(g_ts + n * 3 + 1, clampt(smf[O_SCD + elo * 4 + 1] * qlo));
                atomicAdd(g_ts + n * 3 + 2, clampt(smf[O_SCD + elo * 4 + 2] * qlo));
                atomicAdd(g_cnt + n, 1.0f);
            }
            if (e0 + ehi < EDGES) {
                int n = sRow[ehi];
                atomicAdd(g_ts + n * 3 + 0, clampt(smf[O_SCD + ehi * 4 + 0] * qhi));
                atomicAdd(g_ts + n * 3 + 1, clampt(smf[O_SCD + ehi * 4 + 1] * qhi));
                atomicAdd(g_ts + n * 3 + 2, clampt(smf[O_SCD + ehi * 4 + 2] * qhi));
                atomicAdd(g_cnt + n, 1.0f);
            }
        }
    }
}

// ---------------- node kernel (FFMA2 version, unchanged) ----------------
#define SROWN 36
__device__ __forceinline__ ull pk2(float lo, float hi) {
    ull r; asm("mov.b64 %0, {%1, %2};" : "=l"(r) : "f"(lo), "f"(hi)); return r;
}
__device__ __forceinline__ void upk2(ull v, float& lo, float& hi) {
    asm("mov.b64 {%0, %1}, %2;" : "=f"(lo), "=f"(hi) : "l"(v));
}
__device__ __forceinline__ void fma2(ull& d, ull a, ull b) {
    asm("fma.rn.f32x2 %0, %1, %2, %0;" : "+l"(d) : "l"(a), "l"(b));
}
__device__ __forceinline__ void gemm_step(ull acc[16], const float* xrow, ull ww) {
    const ulonglong2* p = (const ulonglong2*)xrow;
    #pragma unroll
    for (int ep = 0; ep < 8; ep++) {
        ulonglong2 v = p[ep];
        fma2(acc[2 * ep + 0], v.x, ww);
        fma2(acc[2 * ep + 1], v.y, ww);
    }
}

#define SXN   0
#define SMIDN (256 * SROWN)
#define NSM_FLOATS (SMIDN + 128 * SROWN)

__global__ void __launch_bounds__(128, 4) node_kernel(
    const float* __restrict__ h, const float* __restrict__ coord,
    const float* __restrict__ Wn1, const float* __restrict__ bn1,
    const float* __restrict__ Wn2, const float* __restrict__ bn2,
    float* __restrict__ h_out, float* __restrict__ coord_out)
{
    extern __shared__ float sm[];
    const int tid  = threadIdx.x;
    const int lane = tid & 31;
    const int warp = tid >> 5;
    const int n0 = blockIdx.x * 32;

    for (int i = 0; i < 8; i++) {
        int nl = warp * 8 + i;
        int n = n0 + nl;
        if (n < NODES) {
            #pragma unroll
            for (int k0 = 0; k0 < 4; k0++) {
                int k = k0 * 32 + lane;
                sm[SXN + k * SROWN + nl]         = h[(long long)n * D + k];
                sm[SXN + (128 + k) * SROWN + nl] = g_agg[(long long)n * D + k];
            }
        } else {
            #pragma unroll
            for (int k0 = 0; k0 < 4; k0++) {
                int k = k0 * 32 + lane;
                sm[SXN + k * SROWN + nl]         = 0.0f;
                sm[SXN + (128 + k) * SROWN + nl] = 0.0f;
            }
        }
    }
    __syncthreads();

    const int j = tid;
    ull acc[16];
    {
        float b = bn1[j];
        ull bb = pk2(b, b);
        #pragma unroll
        for (int i = 0; i < 16; i++) acc[i] = bb;
        #pragma unroll 4
        for (int k = 0; k < 256; k++) {
            float w = Wn1[k * D + j];
            gemm_step(acc, sm + SXN + k * SROWN, pk2(w, w));
        }
        #pragma unroll
        for (int i = 0; i < 16; i++) {
            float f0, f1; upk2(acc[i], f0, f1);
            *(ull*)(sm + SMIDN + j * SROWN + 2 * i) = pk2(silu_f(f0), silu_f(f1));
        }
    }
    __syncthreads();
    {
        float b = bn2[j];
        ull bb = pk2(b, b);
        #pragma unroll
        for (int i = 0; i < 16; i++) acc[i] = bb;
        #pragma unroll 4
        for (int k = 0; k < 128; k++) {
            float w = Wn2[k * D + j];
            gemm_step(acc, sm + SMIDN + k * SROWN, pk2(w, w));
        }
        #pragma unroll
        for (int i = 0; i < 16; i++) {
            float f0, f1; upk2(acc[i], f0, f1);
            int na = n0 + 2 * i, nb = na + 1;
            if (na < NODES) h_out[(long long)na * D + j] = h[(long long)na * D + j] + f0;
            if (nb < NODES) h_out[(long long)nb * D + j] = h[(long long)nb * D + j] + f1;
        }
    }

    if (tid < 32) {
        int n = n0 + tid;
        if (n < NODES) {
            float cden = fmaxf(g_cnt[n], 1.0f);
            #pragma unroll
            for (int d3 = 0; d3 < 3; d3++) {
                float a = g_ts[n * 3 + d3] / cden;
                a = fminf(fmaxf(a, -MAXT), MAXT);
                coord_out[n * 3 + d3] = coord[n * 3 + d3] + a;
            }
        }
    }
}

// ---------------- launch ----------------
extern "C" void kernel_launch(void* const* d_in, const int* in_sizes, int n_in,
                              void* d_out, int out_size)
{
    const float* h     = (const float*)d_in[0];
    const int*   ei    = (const int*)d_in[1];
    const float* coord = (const float*)d_in[2];
    const float* We1   = (const float*)d_in[3];
    const float* be1   = (const float*)d_in[4];
    const float* We2   = (const float*)d_in[5];
    const float* be2   = (const float*)d_in[6];
    const float* Watt  = (const float*)d_in[7];
    const float* batt  = (const float*)d_in[8];
    const float* Wc1   = (const float*)d_in[9];
    const float* bc1   = (const float*)d_in[10];
    const float* Wc2   = (const float*)d_in[11];
    const float* Wn1   = (const float*)d_in[12];
    const float* bn1   = (const float*)d_in[13];
    const float* Wn2   = (const float*)d_in[14];
    const float* bn2   = (const float*)d_in[15];

    float* out       = (float*)d_out;
    float* h_out     = out;
    float* coord_out = out + (size_t)NODES * D;
    float* edge_out  = coord_out + (size_t)NODES * 3;

    size_t esm = (size_t)ESM_WORDS * sizeof(uint32_t);      // ~106 KB
    size_t nsm = (size_t)NSM_FLOATS * sizeof(float);

    cudaFuncSetAttribute(edge_kernel, cudaFuncAttributeMaxDynamicSharedMemorySize, (int)esm);
    cudaFuncSetAttribute(node_kernel, cudaFuncAttributeMaxDynamicSharedMemorySize, (int)nsm);

    zero_kernel<<<512, 256>>>();
    int prep_threads = NKS1 * 8 * 32 + 2 * NKS2 * 8 * 32;
    prep_kernel<<<(prep_threads + 255) / 256, 256>>>(We1, be1, We2, be2, Wc1, bc1);
    edge_kernel<<<(EDGES + TE - 1) / TE, 128, esm>>>(h, ei, coord, Watt, batt, Wc2, edge_out);
    node_kernel<<<(NODES + 31) / 32, 128, nsm>>>(h, coord, Wn1, bn1, Wn2, bn2, h_out, coord_out);
}

// round 7
// speedup vs baseline: 2.9846x; 1.5047x over previous
#include <cuda_runtime.h>
#include <stdint.h>

#define D 128
#define NODES 50000
#define EDGES 500000
#define MAXT 10.0f

#define TE 64
#define RS1 268          // K-dim stride (264 cols used; mod32=12 -> conflict-free)
#define RS2 140          // (136 cols used; mod32=12)
#define NKS1 33          // K=264/8
#define NKS2 17          // K=136/8

// ---------------- device scratch ----------------
__device__ float g_agg[(size_t)NODES * D];
__device__ float g_ts[(size_t)NODES * 3];
__device__ float g_cnt[NODES];
__device__ float4 g_wf1[NKS1 * 8 * 32];   // We1+be1 fragments
__device__ float4 g_wf2[NKS2 * 8 * 32];   // We2+be2
__device__ float4 g_wf3[NKS2 * 8 * 32];   // Wc1+bc1
__device__ float4 g_wf4[NKS1 * 8 * 32];   // Wn1+bn1
__device__ float4 g_wf5[NKS2 * 8 * 32];   // Wn2+bn2

// ---------------- helpers ----------------
__device__ __forceinline__ float silu_f(float x) {
    return x * __fdividef(1.0f, 1.0f + __expf(-x));
}
__device__ __forceinline__ float sigmoid_f(float x) {
    return __fdividef(1.0f, 1.0f + __expf(-x));
}
__device__ __forceinline__ float clampt(float x) {
    return fminf(fmaxf(x, -MAXT), MAXT);
}
__device__ __forceinline__ uint32_t tfbits(float x) {
    uint32_t u; asm("cvt.rna.tf32.f32 %0, %1;" : "=r"(u) : "f"(x)); return u;
}
__device__ __forceinline__ float tf32r(float x) { return __uint_as_float(tfbits(x)); }

__device__ __forceinline__ void mma8(float acc[4],
    uint32_t a0, uint32_t a1, uint32_t a2, uint32_t a3, uint32_t b0, uint32_t b1)
{
    asm volatile(
        "mma.sync.aligned.m16n8k8.row.col.f32.tf32.tf32.f32 "
        "{%0,%1,%2,%3}, {%4,%5,%6,%7}, {%8,%9}, {%0,%1,%2,%3};"
        : "+f"(acc[0]), "+f"(acc[1]), "+f"(acc[2]), "+f"(acc[3])
        : "r"(a0), "r"(a1), "r"(a2), "r"(a3), "r"(b0), "r"(b1));
}

// Warp computes: acc[mt][ntl] = A[all 64 rows] @ B[this warp's 32 cols]
// wq = frag base + 64*warp + lane  (covers frag pairs p=2w, 2w+1)
template<int NKS>
__device__ __forceinline__ void run_layer_ns(
    const uint32_t* __restrict__ sact, int rs,
    const float4* __restrict__ wq,
    float acc[4][4][4], int r4, int c)
{
    const uint32_t* a0p = sact + r4 * rs + c;
    #pragma unroll 2
    for (int ks = 0; ks < NKS; ks++) {
        float4 b0 = wq[ks * 256];
        float4 b1 = wq[ks * 256 + 32];
        uint32_t a[4][4];
        #pragma unroll
        for (int mt = 0; mt < 4; mt++) {
            const uint32_t* p = a0p + mt * 16 * rs + ks * 8;
            a[mt][0] = p[0];
            a[mt][1] = p[8 * rs];
            a[mt][2] = p[4];
            a[mt][3] = p[8 * rs + 4];
        }
        #pragma unroll
        for (int mt = 0; mt < 4; mt++) {
            mma8(acc[mt][0], a[mt][0], a[mt][1], a[mt][2], a[mt][3],
                 __float_as_uint(b0.x), __float_as_uint(b0.y));
            mma8(acc[mt][1], a[mt][0], a[mt][1], a[mt][2], a[mt][3],
                 __float_as_uint(b0.z), __float_as_uint(b0.w));
            mma8(acc[mt][2], a[mt][0], a[mt][1], a[mt][2], a[mt][3],
                 __float_as_uint(b1.x), __float_as_uint(b1.y));
            mma8(acc[mt][3], a[mt][0], a[mt][1], a[mt][2], a[mt][3],
                 __float_as_uint(b1.z), __float_as_uint(b1.w));
        }
    }
}

// ---------------- zero + weight prep ----------------
__global__ void zero_kernel() {
    int idx = blockIdx.x * blockDim.x + threadIdx.x;
    int stride = gridDim.x * blockDim.x;
    for (int i = idx; i < NODES * D; i += stride) g_agg[i] = 0.0f;
    for (int i = idx; i < NODES * 3; i += stride) g_ts[i] = 0.0f;
    for (int i = idx; i < NODES; i += stride) g_cnt[i] = 0.0f;
}

__device__ __forceinline__ float wb(const float* W, const float* b, int K, int k, int n) {
    if (k < K) return W[k * D + n];
    if (k == K) return b[n];
    return 0.0f;
}

__global__ void prep_kernel(
    const float* __restrict__ We1, const float* __restrict__ be1,
    const float* __restrict__ We2, const float* __restrict__ be2,
    const float* __restrict__ Wc1, const float* __restrict__ bc1,
    const float* __restrict__ Wn1, const float* __restrict__ bn1,
    const float* __restrict__ Wn2, const float* __restrict__ bn2)
{
    int t = blockIdx.x * blockDim.x + threadIdx.x;
    const int n1 = NKS1 * 8 * 32, n2 = NKS2 * 8 * 32;
    const float *W, *bi; int K; float4* dst; int idx;
    if (t < n1)                    { W = We1; bi = be1; K = 257; dst = g_wf1; idx = t; }
    else if (t < n1 + n2)          { W = We2; bi = be2; K = 128; dst = g_wf2; idx = t - n1; }
    else if (t < n1 + 2 * n2)      { W = Wc1; bi = bc1; K = 128; dst = g_wf3; idx = t - n1 - n2; }
    else if (t < 2 * n1 + 2 * n2)  { W = Wn1; bi = bn1; K = 256; dst = g_wf4; idx = t - n1 - 2 * n2; }
    else if (t < 2 * n1 + 3 * n2)  { W = Wn2; bi = bn2; K = 128; dst = g_wf5; idx = t - 2 * n1 - 2 * n2; }
    else return;
    int lane = idx & 31, p = (idx >> 5) & 7, ks = idx >> 8;
    int c = lane & 3, r = lane >> 2, k0 = ks * 8;
    float4 v;
    v.x = tf32r(wb(W, bi, K, k0 + c,     p * 16 + r));
    v.y = tf32r(wb(W, bi, K, k0 + 4 + c, p * 16 + r));
    v.z = tf32r(wb(W, bi, K, k0 + c,     p * 16 + 8 + r));
    v.w = tf32r(wb(W, bi, K, k0 + 4 + c, p * 16 + 8 + r));
    dst[idx] = v;
}

// ---------------- edge kernel ----------------
#define O_SA    0
#define O_SMID  (TE * RS1)                   // 17152
#define O_SCD   (O_SMID + TE * RS2)          // 26112
#define O_ATTP  (O_SCD + TE * 4)             // 26368
#define O_CWP   (O_ATTP + 4 * TE)            // 26624
#define O_SATT  (O_CWP + 4 * TE)             // 26880
#define O_SROW  (O_SATT + TE)                // 26944
#define O_SCOL  (O_SROW + TE)                // 27008
#define ESM_WORDS (O_SCOL + TE)              // 27072 words = 108288 B -> 2 CTA/SM
#define O_SEF   O_SA                         // reuse sA region with stride RS2

__global__ void __launch_bounds__(128) edge_kernel(
    const float* __restrict__ h, const int* __restrict__ ei,
    const float* __restrict__ coord,
    const float* __restrict__ Watt, const float* __restrict__ batt,
    const float* __restrict__ Wc2,
    float* __restrict__ edge_out)
{
    extern __shared__ uint32_t smu[];
    float* smf = (float*)smu;
    int*   sRow = (int*)(smu + O_SROW);
    int*   sCol = (int*)(smu + O_SCOL);

    const int tid  = threadIdx.x;
    const int lane = tid & 31;
    const int warp = tid >> 5;
    const int c    = lane & 3;
    const int r4   = lane >> 2;
    const long long e0 = (long long)blockIdx.x * TE;

    // ---- indices, coord_diff, radial/bias tail cols ----
    if (lane < 16) {
        int el = warp * 16 + lane;
        long long e = e0 + el;
        int rr = 0, cc = 0; float dx = 0, dy = 0, dz = 0, rad = 0;
        if (e < EDGES) {
            rr = ei[e]; cc = ei[(long long)EDGES + e];
            dx = coord[rr * 3 + 0] - coord[cc * 3 + 0];
            dy = coord[rr * 3 + 1] - coord[cc * 3 + 1];
            dz = coord[rr * 3 + 2] - coord[cc * 3 + 2];
            rad = dx * dx + dy * dy + dz * dz;
        }
        sRow[el] = rr; sCol[el] = cc;
        smf[O_SCD + el * 4 + 0] = dx;
        smf[O_SCD + el * 4 + 1] = dy;
        smf[O_SCD + el * 4 + 2] = dz;
        *(float4*)(smf + O_SA + el * RS1 + 256) = make_float4(tf32r(rad), 1.0f, 0.0f, 0.0f);
        *(float4*)(smf + O_SA + el * RS1 + 260) = make_float4(0.0f, 0.0f, 0.0f, 0.0f);
    }
    __syncwarp();

    // ---- gather h[row], h[col] -> sA (tf32), warp w fills rows w*16..+16 ----
    for (int i = 0; i < 16; i++) {
        int el = warp * 16 + i;
        int rr = sRow[el], cc = sCol[el];
        float4 v = *(const float4*)(h + (long long)rr * D + lane * 4);
        float4 w = *(const float4*)(h + (long long)cc * D + lane * 4);
        *(float4*)(smf + O_SA + el * RS1 + lane * 4) =
            make_float4(tf32r(v.x), tf32r(v.y), tf32r(v.z), tf32r(v.w));
        *(float4*)(smf + O_SA + el * RS1 + 128 + lane * 4) =
            make_float4(tf32r(w.x), tf32r(w.y), tf32r(w.z), tf32r(w.w));
    }
    __syncthreads();

    float acc[4][4][4];
    #pragma unroll
    for (int m = 0; m < 4; m++)
        #pragma unroll
        for (int n = 0; n < 4; n++)
            { acc[m][n][0]=0; acc[m][n][1]=0; acc[m][n][2]=0; acc[m][n][3]=0; }

    // ================= Layer 1 =================
    run_layer_ns<NKS1>(smu + O_SA, RS1, g_wf1 + 64 * warp + lane, acc, r4, c);

    #pragma unroll
    for (int mt = 0; mt < 4; mt++) {
        int rlo = mt * 16 + r4;
        #pragma unroll
        for (int nt = 0; nt < 4; nt++) {
            int n0 = warp * 32 + nt * 8 + 2 * c;
            *(uint2*)(smu + O_SMID + rlo * RS2 + n0) =
                make_uint2(tfbits(silu_f(acc[mt][nt][0])), tfbits(silu_f(acc[mt][nt][1])));
            *(uint2*)(smu + O_SMID + (rlo + 8) * RS2 + n0) =
                make_uint2(tfbits(silu_f(acc[mt][nt][2])), tfbits(silu_f(acc[mt][nt][3])));
            acc[mt][nt][0]=0; acc[mt][nt][1]=0; acc[mt][nt][2]=0; acc[mt][nt][3]=0;
        }
    }
    if (lane < 16) {
        int row = warp * 16 + lane;
        *(float4*)(smf + O_SMID + row * RS2 + 128) = make_float4(1.0f, 0, 0, 0);
        *(float4*)(smf + O_SMID + row * RS2 + 132) = make_float4(0, 0, 0, 0);
    }
    __syncthreads();

    // ================= Layer 2 =================
    run_layer_ns<NKS2>(smu + O_SMID, RS2, g_wf2 + 64 * warp + lane, acc, r4, c);

    // attention partials (keep silu'd values in acc)
    {
        float plo[4] = {0,0,0,0}, phi[4] = {0,0,0,0};
        #pragma unroll
        for (int mt = 0; mt < 4; mt++) {
            #pragma unroll
            for (int nt = 0; nt < 4; nt++) {
                int n0 = warp * 32 + nt * 8 + 2 * c;
                float2 wa = *(const float2*)(Watt + n0);
                acc[mt][nt][0] = silu_f(acc[mt][nt][0]);
                acc[mt][nt][1] = silu_f(acc[mt][nt][1]);
                acc[mt][nt][2] = silu_f(acc[mt][nt][2]);
                acc[mt][nt][3] = silu_f(acc[mt][nt][3]);
                plo[mt] += acc[mt][nt][0] * wa.x + acc[mt][nt][1] * wa.y;
                phi[mt] += acc[mt][nt][2] * wa.x + acc[mt][nt][3] * wa.y;
            }
        }
        #pragma unroll
        for (int mt = 0; mt < 4; mt++) {
            plo[mt] += __shfl_xor_sync(0xffffffffu, plo[mt], 1);
            plo[mt] += __shfl_xor_sync(0xffffffffu, plo[mt], 2);
            phi[mt] += __shfl_xor_sync(0xffffffffu, phi[mt], 1);
            phi[mt] += __shfl_xor_sync(0xffffffffu, phi[mt], 2);
        }
        if (c == 0) {
            #pragma unroll
            for (int mt = 0; mt < 4; mt++) {
                smf[O_ATTP + warp * 64 + mt * 16 + r4]     = plo[mt];
                smf[O_ATTP + warp * 64 + mt * 16 + 8 + r4] = phi[mt];
            }
        }
    }
    __syncthreads();
    if (tid < 64) {
        float s = smf[O_ATTP + tid] + smf[O_ATTP + 64 + tid] +
                  smf[O_ATTP + 128 + tid] + smf[O_ATTP + 192 + tid];
        smf[O_SATT + tid] = sigmoid_f(s + batt[0]);
    }
    __syncthreads();

    // apply attention: edge_out + agg atomics + sEf (tf32, for layer 3)
    #pragma unroll
    for (int mt = 0; mt < 4; mt++) {
        int elo = mt * 16 + r4, ehi = elo + 8;
        float attlo = smf[O_SATT + elo], atthi = smf[O_SATT + ehi];
        bool vlo = (e0 + elo) < EDGES, vhi = (e0 + ehi) < EDGES;
        long long glo = (long long)sRow[elo] * D;
        long long ghi = (long long)sRow[ehi] * D;
        float* out_lo = edge_out + (e0 + elo) * D;
        float* out_hi = edge_out + (e0 + ehi) * D;
        #pragma unroll
        for (int nt = 0; nt < 4; nt++) {
            int n0 = warp * 32 + nt * 8 + 2 * c;
            float f0 = acc[mt][nt][0] * attlo, f1 = acc[mt][nt][1] * attlo;
            float f2 = acc[mt][nt][2] * atthi, f3 = acc[mt][nt][3] * atthi;
            if (vlo) {
                *(float2*)(out_lo + n0) = make_float2(f0, f1);
                atomicAdd(g_agg + glo + n0,     f0);
                atomicAdd(g_agg + glo + n0 + 1, f1);
            }
            if (vhi) {
                *(float2*)(out_hi + n0) = make_float2(f2, f3);
                atomicAdd(g_agg + ghi + n0,     f2);
                atomicAdd(g_agg + ghi + n0 + 1, f3);
            }
            *(uint2*)(smu + O_SEF + elo * RS2 + n0) = make_uint2(tfbits(f0), tfbits(f1));
            *(uint2*)(smu + O_SEF + ehi * RS2 + n0) = make_uint2(tfbits(f2), tfbits(f3));
            acc[mt][nt][0]=0; acc[mt][nt][1]=0; acc[mt][nt][2]=0; acc[mt][nt][3]=0;
        }
    }
    if (lane < 16) {
        int row = warp * 16 + lane;
        *(float4*)(smf + O_SEF + row * RS2 + 128) = make_float4(1.0f, 0, 0, 0);
        *(float4*)(smf + O_SEF + row * RS2 + 132) = make_float4(0, 0, 0, 0);
    }
    __syncthreads();

    // ================= Layer 3 (coord MLP) =================
    run_layer_ns<NKS2>(smu + O_SEF, RS2, g_wf3 + 64 * warp + lane, acc, r4, c);
    {
        float qlo[4] = {0,0,0,0}, qhi[4] = {0,0,0,0};
        #pragma unroll
        for (int mt = 0; mt < 4; mt++) {
            #pragma unroll
            for (int nt = 0; nt < 4; nt++) {
                int n0 = warp * 32 + nt * 8 + 2 * c;
                float2 w2 = *(const float2*)(Wc2 + n0);
                qlo[mt] += silu_f(acc[mt][nt][0]) * w2.x + silu_f(acc[mt][nt][1]) * w2.y;
                qhi[mt] += silu_f(acc[mt][nt][2]) * w2.x + silu_f(acc[mt][nt][3]) * w2.y;
            }
        }
        #pragma unroll
        for (int mt = 0; mt < 4; mt++) {
            qlo[mt] += __shfl_xor_sync(0xffffffffu, qlo[mt], 1);
            qlo[mt] += __shfl_xor_sync(0xffffffffu, qlo[mt], 2);
            qhi[mt] += __shfl_xor_sync(0xffffffffu, qhi[mt], 1);
            qhi[mt] += __shfl_xor_sync(0xffffffffu, qhi[mt], 2);
        }
        if (c == 0) {
            #pragma unroll
            for (int mt = 0; mt < 4; mt++) {
                smf[O_CWP + warp * 64 + mt * 16 + r4]     = qlo[mt];
                smf[O_CWP + warp * 64 + mt * 16 + 8 + r4] = qhi[mt];
            }
        }
    }
    __syncthreads();
    if (tid < 64 && (e0 + tid) < EDGES) {
        float cw = smf[O_CWP + tid] + smf[O_CWP + 64 + tid] +
                   smf[O_CWP + 128 + tid] + smf[O_CWP + 192 + tid];
        int n = sRow[tid];
        atomicAdd(g_ts + n * 3 + 0, clampt(smf[O_SCD + tid * 4 + 0] * cw));
        atomicAdd(g_ts + n * 3 + 1, clampt(smf[O_SCD + tid * 4 + 1] * cw));
        atomicAdd(g_ts + n * 3 + 2, clampt(smf[O_SCD + tid * 4 + 2] * cw));
        atomicAdd(g_cnt + n, 1.0f);
    }
}

// ---------------- node kernel (same MMA machinery) ----------------
#define TN 64
#define O_XN    0
#define O_MIDN  (TN * RS1)                   // 17152
#define NSM_WORDS (O_MIDN + TN * RS2)        // 26112 words = 104448 B -> 2 CTA/SM

__global__ void __launch_bounds__(128) node_kernel(
    const float* __restrict__ h, const float* __restrict__ coord,
    float* __restrict__ h_out, float* __restrict__ coord_out)
{
    extern __shared__ uint32_t smu[];
    float* smf = (float*)smu;

    const int tid  = threadIdx.x;
    const int lane = tid & 31;
    const int warp = tid >> 5;
    const int c    = lane & 3;
    const int r4   = lane >> 2;
    const int n0b  = blockIdx.x * TN;

    // gather [h | agg] -> sXN (tf32), warp w fills rows w*16..+16
    for (int i = 0; i < 16; i++) {
        int row = warp * 16 + i;
        int n = n0b + row;
        float4 tv = make_float4(0, 0, 0, 0), tw = make_float4(0, 0, 0, 0);
        if (n < NODES) {
            float4 v = *(const float4*)(h + (long long)n * D + lane * 4);
            float4 w = *(const float4*)(g_agg + (long long)n * D + lane * 4);
            tv = make_float4(tf32r(v.x), tf32r(v.y), tf32r(v.z), tf32r(v.w));
            tw = make_float4(tf32r(w.x), tf32r(w.y), tf32r(w.z), tf32r(w.w));
        }
        *(float4*)(smf + O_XN + row * RS1 + lane * 4) = tv;
        *(float4*)(smf + O_XN + row * RS1 + 128 + lane * 4) = tw;
    }
    if (lane < 16) {
        int row = warp * 16 + lane;
        *(float4*)(smf + O_XN + row * RS1 + 256) = make_float4(1.0f, 0, 0, 0);
        *(float4*)(smf + O_XN + row * RS1 + 260) = make_float4(0, 0, 0, 0);
    }
    __syncthreads();

    float acc[4][4][4];
    #pragma unroll
    for (int m = 0; m < 4; m++)
        #pragma unroll
        for (int n = 0; n < 4; n++)
            { acc[m][n][0]=0; acc[m][n][1]=0; acc[m][n][2]=0; acc[m][n][3]=0; }

    run_layer_ns<NKS1>(smu + O_XN, RS1, g_wf4 + 64 * warp + lane, acc, r4, c);

    #pragma unroll
    for (int mt = 0; mt < 4; mt++) {
        int rlo = mt * 16 + r4;
        #pragma unroll
        for (int nt = 0; nt < 4; nt++) {
            int n0 = warp * 32 + nt * 8 + 2 * c;
            *(uint2*)(smu + O_MIDN + rlo * RS2 + n0) =
                make_uint2(tfbits(silu_f(acc[mt][nt][0])), tfbits(silu_f(acc[mt][nt][1])));
            *(uint2*)(smu + O_MIDN + (rlo + 8) * RS2 + n0) =
                make_uint2(tfbits(silu_f(acc[mt][nt][2])), tfbits(silu_f(acc[mt][nt][3])));
            acc[mt][nt][0]=0; acc[mt][nt][1]=0; acc[mt][nt][2]=0; acc[mt][nt][3]=0;
        }
    }
    if (lane < 16) {
        int row = warp * 16 + lane;
        *(float4*)(smf + O_MIDN + row * RS2 + 128) = make_float4(1.0f, 0, 0, 0);
        *(float4*)(smf + O_MIDN + row * RS2 + 132) = make_float4(0, 0, 0, 0);
    }
    __syncthreads();

    run_layer_ns<NKS2>(smu + O_MIDN, RS2, g_wf5 + 64 * warp + lane, acc, r4, c);

    // h_out = h + acc
    #pragma unroll
    for (int mt = 0; mt < 4; mt++) {
        int nlo = n0b + mt * 16 + r4, nhi = nlo + 8;
        #pragma unroll
        for (int nt = 0; nt < 4; nt++) {
            int n0 = warp * 32 + nt * 8 + 2 * c;
            if (nlo < NODES) {
                float2 hv = *(const float2*)(h + (long long)nlo * D + n0);
                *(float2*)(h_out + (long long)nlo * D + n0) =
                    make_float2(hv.x + acc[mt][nt][0], hv.y + acc[mt][nt][1]);
            }
            if (nhi < NODES) {
                float2 hv = *(const float2*)(h + (long long)nhi * D + n0);
                *(float2*)(h_out + (long long)nhi * D + n0) =
                    make_float2(hv.x + acc[mt][nt][2], hv.y + acc[mt][nt][3]);
            }
        }
    }

    // coord_out = coord + clip(mean(trans))
    if (tid < TN) {
        int n = n0b + tid;
        if (n < NODES) {
            float cden = fmaxf(g_cnt[n], 1.0f);
            #pragma unroll
            for (int d3 = 0; d3 < 3; d3++) {
                float a = g_ts[n * 3 + d3] / cden;
                a = fminf(fmaxf(a, -MAXT), MAXT);
                coord_out[n * 3 + d3] = coord[n * 3 + d3] + a;
            }
        }
    }
}

// ---------------- launch ----------------
extern "C" void kernel_launch(void* const* d_in, const int* in_sizes, int n_in,
                              void* d_out, int out_size)
{
    const float* h     = (const float*)d_in[0];
    const int*   ei    = (const int*)d_in[1];
    const float* coord = (const float*)d_in[2];
    const float* We1   = (const float*)d_in[3];
    const float* be1   = (const float*)d_in[4];
    const float* We2   = (const float*)d_in[5];
    const float* be2   = (const float*)d_in[6];
    const float* Watt  = (const float*)d_in[7];
    const float* batt  = (const float*)d_in[8];
    const float* Wc1   = (const float*)d_in[9];
    const float* bc1   = (const float*)d_in[10];
    const float* Wc2   = (const float*)d_in[11];
    const float* Wn1   = (const float*)d_in[12];
    const float* bn1   = (const float*)d_in[13];
    const float* Wn2   = (const float*)d_in[14];
    const float* bn2   = (const float*)d_in[15];

    float* out       = (float*)d_out;
    float* h_out     = out;
    float* coord_out = out + (size_t)NODES * D;
    float* edge_out  = coord_out + (size_t)NODES * 3;

    size_t esm = (size_t)ESM_WORDS * sizeof(uint32_t);
    size_t nsm = (size_t)NSM_WORDS * sizeof(uint32_t);

    cudaFuncSetAttribute(edge_kernel, cudaFuncAttributeMaxDynamicSharedMemorySize, (int)esm);
    cudaFuncSetAttribute(node_kernel, cudaFuncAttributeMaxDynamicSharedMemorySize, (int)nsm);

    zero_kernel<<<512, 256>>>();
    int prep_threads = 2 * NKS1 * 8 * 32 + 3 * NKS2 * 8 * 32;
    prep_kernel<<<(prep_threads + 255) / 256, 256>>>(
        We1, be1, We2, be2, Wc1, bc1, Wn1, bn1, Wn2, bn2);
    edge_kernel<<<(EDGES + TE - 1) / TE, 128, esm>>>(h, ei, coord, Watt, batt, Wc2, edge_out);
    node_kernel<<<(NODES + TN - 1) / TN, 128, nsm>>>(h, coord, h_out, coord_out);
}

// round 8
// speedup vs baseline: 3.4207x; 1.1461x over previous
#include <cuda_runtime.h>
#include <stdint.h>

#define D 128
#define NODES 50000
#define EDGES 500000
#define MAXT 10.0f

#define TE 64
#define NTH 256
#define RS1 268          // K-dim stride (264 cols used; mod32=12 -> conflict-free)
#define RS2 140          // (136 cols used; mod32=12)
#define NKS1 33          // K=264/8
#define NKS2 17          // K=136/8

// ---------------- device scratch ----------------
__device__ float g_agg[(size_t)NODES * D];
__device__ float g_ts[(size_t)NODES * 3];
__device__ float g_cnt[NODES];
__device__ float4 g_wf1[NKS1 * 8 * 32];   // We1+be1 fragments
__device__ float4 g_wf2[NKS2 * 8 * 32];   // We2+be2
__device__ float4 g_wf3[NKS2 * 8 * 32];   // Wc1+bc1
__device__ float4 g_wf4[NKS1 * 8 * 32];   // Wn1+bn1
__device__ float4 g_wf5[NKS2 * 8 * 32];   // Wn2+bn2

// ---------------- helpers ----------------
__device__ __forceinline__ float silu_f(float x) {
    return x * __fdividef(1.0f, 1.0f + __expf(-x));
}
__device__ __forceinline__ float sigmoid_f(float x) {
    return __fdividef(1.0f, 1.0f + __expf(-x));
}
__device__ __forceinline__ float clampt(float x) {
    return fminf(fmaxf(x, -MAXT), MAXT);
}
__device__ __forceinline__ uint32_t tfbits(float x) {
    uint32_t u; asm("cvt.rna.tf32.f32 %0, %1;" : "=r"(u) : "f"(x)); return u;
}
__device__ __forceinline__ float tf32r(float x) { return __uint_as_float(tfbits(x)); }

__device__ __forceinline__ void red2(float* p, float a, float b) {
    asm volatile("red.global.add.v2.f32 [%0], {%1, %2};"
                 :: "l"(p), "f"(a), "f"(b) : "memory");
}

__device__ __forceinline__ void mma8(float acc[4],
    uint32_t a0, uint32_t a1, uint32_t a2, uint32_t a3, uint32_t b0, uint32_t b1)
{
    asm volatile(
        "mma.sync.aligned.m16n8k8.row.col.f32.tf32.tf32.f32 "
        "{%0,%1,%2,%3}, {%4,%5,%6,%7}, {%8,%9}, {%0,%1,%2,%3};"
        : "+f"(acc[0]), "+f"(acc[1]), "+f"(acc[2]), "+f"(acc[3])
        : "r"(a0), "r"(a1), "r"(a2), "r"(a3), "r"(b0), "r"(b1));
}

// Warp computes: acc[mt][nt] = A[all 64 rows] @ B[this warp's 16 cols]
// wq = frag base + 32*warp + lane
template<int NKS>
__device__ __forceinline__ void run_layer_ns(
    const uint32_t* __restrict__ sact, int rs,
    const float4* __restrict__ wq,
    float acc[4][2][4], int r4, int c)
{
    const uint32_t* a0p = sact + r4 * rs + c;
    #pragma unroll 2
    for (int ks = 0; ks < NKS; ks++) {
        float4 b0 = wq[ks * 256];
        uint32_t a[4][4];
        #pragma unroll
        for (int mt = 0; mt < 4; mt++) {
            const uint32_t* p = a0p + mt * 16 * rs + ks * 8;
            a[mt][0] = p[0];
            a[mt][1] = p[8 * rs];
            a[mt][2] = p[4];
            a[mt][3] = p[8 * rs + 4];
        }
        #pragma unroll
        for (int mt = 0; mt < 4; mt++) {
            mma8(acc[mt][0], a[mt][0], a[mt][1], a[mt][2], a[mt][3],
                 __float_as_uint(b0.x), __float_as_uint(b0.y));
            mma8(acc[mt][1], a[mt][0], a[mt][1], a[mt][2], a[mt][3],
                 __float_as_uint(b0.z), __float_as_uint(b0.w));
        }
    }
}

// ---------------- zero + weight prep ----------------
__global__ void zero_kernel() {
    int idx = blockIdx.x * blockDim.x + threadIdx.x;
    int stride = gridDim.x * blockDim.x;
    for (int i = idx; i < NODES * D; i += stride) g_agg[i] = 0.0f;
    for (int i = idx; i < NODES * 3; i += stride) g_ts[i] = 0.0f;
    for (int i = idx; i < NODES; i += stride) g_cnt[i] = 0.0f;
}

__device__ __forceinline__ float wb(const float* W, const float* b, int K, int k, int n) {
    if (k < K) return W[k * D + n];
    if (k == K) return b[n];
    return 0.0f;
}

__global__ void prep_kernel(
    const float* __restrict__ We1, const float* __restrict__ be1,
    const float* __restrict__ We2, const float* __restrict__ be2,
    const float* __restrict__ Wc1, const float* __restrict__ bc1,
    const float* __restrict__ Wn1, const float* __restrict__ bn1,
    const float* __restrict__ Wn2, const float* __restrict__ bn2)
{
    int t = blockIdx.x * blockDim.x + threadIdx.x;
    const int n1 = NKS1 * 8 * 32, n2 = NKS2 * 8 * 32;
    const float *W, *bi; int K; float4* dst; int idx;
    if (t < n1)                    { W = We1; bi = be1; K = 257; dst = g_wf1; idx = t; }
    else if (t < n1 + n2)          { W = We2; bi = be2; K = 128; dst = g_wf2; idx = t - n1; }
    else if (t < n1 + 2 * n2)      { W = Wc1; bi = bc1; K = 128; dst = g_wf3; idx = t - n1 - n2; }
    else if (t < 2 * n1 + 2 * n2)  { W = Wn1; bi = bn1; K = 256; dst = g_wf4; idx = t - n1 - 2 * n2; }
    else if (t < 2 * n1 + 3 * n2)  { W = Wn2; bi = bn2; K = 128; dst = g_wf5; idx = t - 2 * n1 - 2 * n2; }
    else return;
    int lane = idx & 31, p = (idx >> 5) & 7, ks = idx >> 8;
    int c = lane & 3, r = lane >> 2, k0 = ks * 8;
    float4 v;
    v.x = tf32r(wb(W, bi, K, k0 + c,     p * 16 + r));
    v.y = tf32r(wb(W, bi, K, k0 + 4 + c, p * 16 + r));
    v.z = tf32r(wb(W, bi, K, k0 + c,     p * 16 + 8 + r));
    v.w = tf32r(wb(W, bi, K, k0 + 4 + c, p * 16 + 8 + r));
    dst[idx] = v;
}

// ---------------- edge kernel ----------------
#define O_SA    0
#define O_SMID  (TE * RS1)                   // 17152
#define O_SCD   (O_SMID + TE * RS2)          // 26112
#define O_ATTP  (O_SCD + TE * 4)             // 26368  [8][64]
#define O_CWP   (O_ATTP + 8 * TE)            // 26880  [8][64]
#define O_SATT  (O_CWP + 8 * TE)             // 27392
#define O_SROW  (O_SATT + TE)                // 27456
#define O_SCOL  (O_SROW + TE)                // 27520
#define ESM_WORDS (O_SCOL + TE)              // 27584 words = 110336 B -> 2 CTA/SM
#define O_SEF   O_SA                         // reuse sA region with stride RS2

__global__ void __launch_bounds__(NTH) edge_kernel(
    const float* __restrict__ h, const int* __restrict__ ei,
    const float* __restrict__ coord,
    const float* __restrict__ Watt, const float* __restrict__ batt,
    const float* __restrict__ Wc2,
    float* __restrict__ edge_out)
{
    extern __shared__ uint32_t smu[];
    float* smf = (float*)smu;
    int*   sRow = (int*)(smu + O_SROW);
    int*   sCol = (int*)(smu + O_SCOL);

    const int tid  = threadIdx.x;
    const int lane = tid & 31;
    const int warp = tid >> 5;      // 0..7 = N-slice (16 cols)
    const int c    = lane & 3;
    const int r4   = lane >> 2;
    const long long e0 = (long long)blockIdx.x * TE;

    // ---- indices, coord_diff, radial/bias tail cols ----
    if (tid < TE) {
        int el = tid;
        long long e = e0 + el;
        int rr = 0, cc = 0; float dx = 0, dy = 0, dz = 0, rad = 0;
        if (e < EDGES) {
            rr = ei[e]; cc = ei[(long long)EDGES + e];
            dx = coord[rr * 3 + 0] - coord[cc * 3 + 0];
            dy = coord[rr * 3 + 1] - coord[cc * 3 + 1];
            dz = coord[rr * 3 + 2] - coord[cc * 3 + 2];
            rad = dx * dx + dy * dy + dz * dz;
        }
        sRow[el] = rr; sCol[el] = cc;
        smf[O_SCD + el * 4 + 0] = dx;
        smf[O_SCD + el * 4 + 1] = dy;
        smf[O_SCD + el * 4 + 2] = dz;
        *(float4*)(smf + O_SA + el * RS1 + 256) = make_float4(tf32r(rad), 1.0f, 0.0f, 0.0f);
        *(float4*)(smf + O_SA + el * RS1 + 260) = make_float4(0.0f, 0.0f, 0.0f, 0.0f);
    }
    __syncthreads();

    // ---- gather h[row], h[col] -> sA (tf32), warp w fills rows w*8..+8 ----
    for (int i = 0; i < 8; i++) {
        int el = warp * 8 + i;
        int rr = sRow[el], cc = sCol[el];
        float4 v = *(const float4*)(h + (long long)rr * D + lane * 4);
        float4 w = *(const float4*)(h + (long long)cc * D + lane * 4);
        *(float4*)(smf + O_SA + el * RS1 + lane * 4) =
            make_float4(tf32r(v.x), tf32r(v.y), tf32r(v.z), tf32r(v.w));
        *(float4*)(smf + O_SA + el * RS1 + 128 + lane * 4) =
            make_float4(tf32r(w.x), tf32r(w.y), tf32r(w.z), tf32r(w.w));
    }
    __syncthreads();

    float acc[4][2][4];
    #pragma unroll
    for (int m = 0; m < 4; m++)
        #pragma unroll
        for (int n = 0; n < 2; n++)
            { acc[m][n][0]=0; acc[m][n][1]=0; acc[m][n][2]=0; acc[m][n][3]=0; }

    // ================= Layer 1 =================
    run_layer_ns<NKS1>(smu + O_SA, RS1, g_wf1 + 32 * warp + lane, acc, r4, c);

    #pragma unroll
    for (int mt = 0; mt < 4; mt++) {
        int rlo = mt * 16 + r4;
        #pragma unroll
        for (int nt = 0; nt < 2; nt++) {
            int n0 = warp * 16 + nt * 8 + 2 * c;
            *(uint2*)(smu + O_SMID + rlo * RS2 + n0) =
                make_uint2(tfbits(silu_f(acc[mt][nt][0])), tfbits(silu_f(acc[mt][nt][1])));
            *(uint2*)(smu + O_SMID + (rlo + 8) * RS2 + n0) =
                make_uint2(tfbits(silu_f(acc[mt][nt][2])), tfbits(silu_f(acc[mt][nt][3])));
            acc[mt][nt][0]=0; acc[mt][nt][1]=0; acc[mt][nt][2]=0; acc[mt][nt][3]=0;
        }
    }
    if (tid < TE) {
        *(float4*)(smf + O_SMID + tid * RS2 + 128) = make_float4(1.0f, 0, 0, 0);
        *(float4*)(smf + O_SMID + tid * RS2 + 132) = make_float4(0, 0, 0, 0);
    }
    __syncthreads();

    // ================= Layer 2 =================
    run_layer_ns<NKS2>(smu + O_SMID, RS2, g_wf2 + 32 * warp + lane, acc, r4, c);

    // attention partials (keep silu'd values in acc)
    {
        float plo[4] = {0,0,0,0}, phi[4] = {0,0,0,0};
        #pragma unroll
        for (int mt = 0; mt < 4; mt++) {
            #pragma unroll
            for (int nt = 0; nt < 2; nt++) {
                int n0 = warp * 16 + nt * 8 + 2 * c;
                float2 wa = *(const float2*)(Watt + n0);
                acc[mt][nt][0] = silu_f(acc[mt][nt][0]);
                acc[mt][nt][1] = silu_f(acc[mt][nt][1]);
                acc[mt][nt][2] = silu_f(acc[mt][nt][2]);
                acc[mt][nt][3] = silu_f(acc[mt][nt][3]);
                plo[mt] += acc[mt][nt][0] * wa.x + acc[mt][nt][1] * wa.y;
                phi[mt] += acc[mt][nt][2] * wa.x + acc[mt][nt][3] * wa.y;
            }
        }
        #pragma unroll
        for (int mt = 0; mt < 4; mt++) {
            plo[mt] += __shfl_xor_sync(0xffffffffu, plo[mt], 1);
            plo[mt] += __shfl_xor_sync(0xffffffffu, plo[mt], 2);
            phi[mt] += __shfl_xor_sync(0xffffffffu, phi[mt], 1);
            phi[mt] += __shfl_xor_sync(0xffffffffu, phi[mt], 2);
        }
        if (c == 0) {
            #pragma unroll
            for (int mt = 0; mt < 4; mt++) {
                smf[O_ATTP + warp * 64 + mt * 16 + r4]     = plo[mt];
                smf[O_ATTP + warp * 64 + mt * 16 + 8 + r4] = phi[mt];
            }
        }
    }
    __syncthreads();
    if (tid < TE) {
        float s = 0.0f;
        #pragma unroll
        for (int w = 0; w < 8; w++) s += smf[O_ATTP + w * 64 + tid];
        smf[O_SATT + tid] = sigmoid_f(s + batt[0]);
    }
    __syncthreads();

    // apply attention: edge_out + agg red.v2 + sEf (tf32, for layer 3)
    #pragma unroll
    for (int mt = 0; mt < 4; mt++) {
        int elo = mt * 16 + r4, ehi = elo + 8;
        float attlo = smf[O_SATT + elo], atthi = smf[O_SATT + ehi];
        bool vlo = (e0 + elo) < EDGES, vhi = (e0 + ehi) < EDGES;
        long long glo = (long long)sRow[elo] * D;
        long long ghi = (long long)sRow[ehi] * D;
        float* out_lo = edge_out + (e0 + elo) * D;
        float* out_hi = edge_out + (e0 + ehi) * D;
        #pragma unroll
        for (int nt = 0; nt < 2; nt++) {
            int n0 = warp * 16 + nt * 8 + 2 * c;
            float f0 = acc[mt][nt][0] * attlo, f1 = acc[mt][nt][1] * attlo;
            float f2 = acc[mt][nt][2] * atthi, f3 = acc[mt][nt][3] * atthi;
            if (vlo) {
                *(float2*)(out_lo + n0) = make_float2(f0, f1);
                red2(g_agg + glo + n0, f0, f1);
            }
            if (vhi) {
                *(float2*)(out_hi + n0) = make_float2(f2, f3);
                red2(g_agg + ghi + n0, f2, f3);
            }
            *(uint2*)(smu + O_SEF + elo * RS2 + n0) = make_uint2(tfbits(f0), tfbits(f1));
            *(uint2*)(smu + O_SEF + ehi * RS2 + n0) = make_uint2(tfbits(f2), tfbits(f3));
            acc[mt][nt][0]=0; acc[mt][nt][1]=0; acc[mt][nt][2]=0; acc[mt][nt][3]=0;
        }
    }
    if (tid < TE) {
        *(float4*)(smf + O_SEF + tid * RS2 + 128) = make_float4(1.0f, 0, 0, 0);
        *(float4*)(smf + O_SEF + tid * RS2 + 132) = make_float4(0, 0, 0, 0);
    }
    __syncthreads();

    // ================= Layer 3 (coord MLP) =================
    run_layer_ns<NKS2>(smu + O_SEF, RS2, g_wf3 + 32 * warp + lane, acc, r4, c);
    {
        float qlo[4] = {0,0,0,0}, qhi[4] = {0,0,0,0};
        #pragma unroll
        for (int mt = 0; mt < 4; mt++) {
            #pragma unroll
            for (int nt = 0; nt < 2; nt++) {
                int n0 = warp * 16 + nt * 8 + 2 * c;
                float2 w2 = *(const float2*)(Wc2 + n0);
                qlo[mt] += silu_f(acc[mt][nt][0]) * w2.x + silu_f(acc[mt][nt][1]) * w2.y;
                qhi[mt] += silu_f(acc[mt][nt][2]) * w2.x + silu_f(acc[mt][nt][3]) * w2.y;
            }
        }
        #pragma unroll
        for (int mt = 0; mt < 4; mt++) {
            qlo[mt] += __shfl_xor_sync(0xffffffffu, qlo[mt], 1);
            qlo[mt] += __shfl_xor_sync(0xffffffffu, qlo[mt], 2);
            qhi[mt] += __shfl_xor_sync(0xffffffffu, qhi[mt], 1);
            qhi[mt] += __shfl_xor_sync(0xffffffffu, qhi[mt], 2);
        }
        if (c == 0) {
            #pragma unroll
            for (int mt = 0; mt < 4; mt++) {
                smf[O_CWP + warp * 64 + mt * 16 + r4]     = qlo[mt];
                smf[O_CWP + warp * 64 + mt * 16 + 8 + r4] = qhi[mt];
            }
        }
    }
    __syncthreads();
    if (tid < TE && (e0 + tid) < EDGES) {
        float cw = 0.0f;
        #pragma unroll
        for (int w = 0; w < 8; w++) cw += smf[O_CWP + w * 64 + tid];
        int n = sRow[tid];
        atomicAdd(g_ts + n * 3 + 0, clampt(smf[O_SCD + tid * 4 + 0] * cw));
        atomicAdd(g_ts + n * 3 + 1, clampt(smf[O_SCD + tid * 4 + 1] * cw));
        atomicAdd(g_ts + n * 3 + 2, clampt(smf[O_SCD + tid * 4 + 2] * cw));
        atomicAdd(g_cnt + n, 1.0f);
    }
}

// ---------------- node kernel ----------------
#define TN 64
#define O_XN    0
#define O_MIDN  (TN * RS1)                   // 17152
#define NSM_WORDS (O_MIDN + TN * RS2)        // 26112 words = 104448 B -> 2 CTA/SM

__global__ void __launch_bounds__(NTH) node_kernel(
    const float* __restrict__ h, const float* __restrict__ coord,
    float* __restrict__ h_out, float* __restrict__ coord_out)
{
    extern __shared__ uint32_t smu[];
    float* smf = (float*)smu;

    const int tid  = threadIdx.x;
    const int lane = tid & 31;
    const int warp = tid >> 5;
    const int c    = lane & 3;
    const int r4   = lane >> 2;
    const int n0b  = blockIdx.x * TN;

    // gather [h | agg] -> sXN (tf32), warp w fills rows w*8..+8
    for (int i = 0; i < 8; i++) {
        int row = warp * 8 + i;
        int n = n0b + row;
        float4 tv = make_float4(0, 0, 0, 0), tw = make_float4(0, 0, 0, 0);
        if (n < NODES) {
            float4 v = *(const float4*)(h + (long long)n * D + lane * 4);
            float4 w = *(const float4*)(g_agg + (long long)n * D + lane * 4);
            tv = make_float4(tf32r(v.x), tf32r(v.y), tf32r(v.z), tf32r(v.w));
            tw = make_float4(tf32r(w.x), tf32r(w.y), tf32r(w.z), tf32r(w.w));
        }
        *(float4*)(smf + O_XN + row * RS1 + lane * 4) = tv;
        *(float4*)(smf + O_XN + row * RS1 + 128 + lane * 4) = tw;
    }
    if (tid < TN) {
        *(float4*)(smf + O_XN + tid * RS1 + 256) = make_float4(1.0f, 0, 0, 0);
        *(float4*)(smf + O_XN + tid * RS1 + 260) = make_float4(0, 0, 0, 0);
    }
    __syncthreads();

    float acc[4][2][4];
    #pragma unroll
    for (int m = 0; m < 4; m++)
        #pragma unroll
        for (int n = 0; n < 2; n++)
            { acc[m][n][0]=0; acc[m][n][1]=0; acc[m][n][2]=0; acc[m][n][3]=0; }

    run_layer_ns<NKS1>(smu + O_XN, RS1, g_wf4 + 32 * warp + lane, acc, r4, c);

    #pragma unroll
    for (int mt = 0; mt < 4; mt++) {
        int rlo = mt * 16 + r4;
        #pragma unroll
        for (int nt = 0; nt < 2; nt++) {
            int n0 = warp * 16 + nt * 8 + 2 * c;
            *(uint2*)(smu + O_MIDN + rlo * RS2 + n0) =
                make_uint2(tfbits(silu_f(acc[mt][nt][0])), tfbits(silu_f(acc[mt][nt][1])));
            *(uint2*)(smu + O_MIDN + (rlo + 8) * RS2 + n0) =
                make_uint2(tfbits(silu_f(acc[mt][nt][2])), tfbits(silu_f(acc[mt][nt][3])));
            acc[mt][nt][0]=0; acc[mt][nt][1]=0; acc[mt][nt][2]=0; acc[mt][nt][3]=0;
        }
    }
    if (tid < TN) {
        *(float4*)(smf + O_MIDN + tid * RS2 + 128) = make_float4(1.0f, 0, 0, 0);
        *(float4*)(smf + O_MIDN + tid * RS2 + 132) = make_float4(0, 0, 0, 0);
    }
    __syncthreads();

    run_layer_ns<NKS2>(smu + O_MIDN, RS2, g_wf5 + 32 * warp + lane, acc, r4, c);

    // h_out = h + acc
    #pragma unroll
    for (int mt = 0; mt < 4; mt++) {
        int nlo = n0b + mt * 16 + r4, nhi = nlo + 8;
        #pragma unroll
        for (int nt = 0; nt < 2; nt++) {
            int n0 = warp * 16 + nt * 8 + 2 * c;
            if (nlo < NODES) {
                float2 hv = *(const float2*)(h + (long long)nlo * D + n0);
                *(float2*)(h_out + (long long)nlo * D + n0) =
                    make_float2(hv.x + acc[mt][nt][0], hv.y + acc[mt][nt][1]);
            }
            if (nhi < NODES) {
                float2 hv = *(const float2*)(h + (long long)nhi * D + n0);
                *(float2*)(h_out + (long long)nhi * D + n0) =
                    make_float2(hv.x + acc[mt][nt][2], hv.y + acc[mt][nt][3]);
            }
        }
    }

    // coord_out = coord + clip(mean(trans))
    if (tid < TN) {
        int n = n0b + tid;
        if (n < NODES) {
            float cden = fmaxf(g_cnt[n], 1.0f);
            #pragma unroll
            for (int d3 = 0; d3 < 3; d3++) {
                float a = g_ts[n * 3 + d3] / cden;
                a = fminf(fmaxf(a, -MAXT), MAXT);
                coord_out[n * 3 + d3] = coord[n * 3 + d3] + a;
            }
        }
    }
}

// ---------------- launch ----------------
extern "C" void kernel_launch(void* const* d_in, const int* in_sizes, int n_in,
                              void* d_out, int out_size)
{
    const float* h     = (const float*)d_in[0];
    const int*   ei    = (const int*)d_in[1];
    const float* coord = (const float*)d_in[2];
    const float* We1   = (const float*)d_in[3];
    const float* be1   = (const float*)d_in[4];
    const float* We2   = (const float*)d_in[5];
    const float* be2   = (const float*)d_in[6];
    const float* Watt  = (const float*)d_in[7];
    const float* batt  = (const float*)d_in[8];
    const float* Wc1   = (const float*)d_in[9];
    const float* bc1   = (const float*)d_in[10];
    const float* Wc2   = (const float*)d_in[11];
    const float* Wn1   = (const float*)d_in[12];
    const float* bn1   = (const float*)d_in[13];
    const float* Wn2   = (const float*)d_in[14];
    const float* bn2   = (const float*)d_in[15];

    float* out       = (float*)d_out;
    float* h_out     = out;
    float* coord_out = out + (size_t)NODES * D;
    float* edge_out  = coord_out + (size_t)NODES * 3;

    size_t esm = (size_t)ESM_WORDS * sizeof(uint32_t);
    size_t nsm = (size_t)NSM_WORDS * sizeof(uint32_t);

    cudaFuncSetAttribute(edge_kernel, cudaFuncAttributeMaxDynamicSharedMemorySize, (int)esm);
    cudaFuncSetAttribute(node_kernel, cudaFuncAttributeMaxDynamicSharedMemorySize, (int)nsm);

    zero_kernel<<<512, 256>>>();
    int prep_threads = 2 * NKS1 * 8 * 32 + 3 * NKS2 * 8 * 32;
    prep_kernel<<<(prep_threads + 255) / 256, 256>>>(
        We1, be1, We2, be2, Wc1, bc1, Wn1, bn1, Wn2, bn2);
    edge_kernel<<<(EDGES + TE - 1) / TE, NTH, esm>>>(h, ei, coord, Watt, batt, Wc2, edge_out);
    node_kernel<<<(NODES + TN - 1) / TN, NTH, nsm>>>(h, coord, h_out, coord_out);
}